// round 6
// baseline (speedup 1.0000x reference)
#include <cuda_runtime.h>
#include <cstdint>

#define B_N   4096
#define D_DIM 1024
#define N_LAT 32768
#define TOPK  64

// k-panel size for bit-exact chunked accumulation (Eigen gebp kc=512):
// total = fl(P0 + P1), each P an ascending-k FFMA chain from fresh 0.
#define KC 512
#define NCHUNK (D_DIM / KC)

// ---- output layout (flattened tuple concat, f32) ----
#define SZ_SAE  ((size_t)B_N * D_DIM)            // 4194304
#define SZ_FEAT ((size_t)B_N * N_LAT)            // 134217728
#define SZ_TA   ((size_t)B_N * TOPK)             // 262144
#define TOTAL_FULL (SZ_SAE + SZ_FEAT + SZ_TA + SZ_TA + 5)   // 138936325
#define TOTAL_NOFEAT (SZ_SAE + SZ_TA + SZ_TA + 5)           // 4718597

// ---- scratch (device globals: no runtime allocation allowed) ----
__device__ float g_top_val[B_N * TOPK];
__device__ int   g_top_idx[B_N * TOPK];
__device__ float g_colsum[D_DIM];
__device__ float g_acc[4];                       // [0]=SSE, [1]=sum x^2
__device__ float g_feat_fallback[(size_t)B_N * N_LAT];

// ============================================================
__global__ void init_kernel() {
    int t = threadIdx.x;
    if (t < 4) g_acc[t] = 0.0f;
}

// ============================================================
__global__ void colstats_kernel(const float* __restrict__ X) {
    int c = blockIdx.x * blockDim.x + threadIdx.x;
    float s = 0.f, q = 0.f;
    #pragma unroll 4
    for (int n = 0; n < B_N; n++) {
        float v = X[(size_t)n * D_DIM + c];
        s += v;
        q += v * v;
    }
    g_colsum[c] = s;
    atomicAdd(&g_acc[1], q);
}

// ============================================================
// encode GEMM: feat[n,l] = relu( sum_d (x[n,d]-b_dec[d]) * W_enc[l,d] + b_enc[l] )
// 128x128x16 tile, 256 threads, 8x8 per thread, f32 FFMA,
// k accumulated in NCHUNK panels of KC (fresh accumulator per panel).
// ============================================================
#define BM 128
#define BN 128
#define BK 16

__global__ __launch_bounds__(256)
void encode_gemm(const float* __restrict__ X, const float* __restrict__ W,
                 const float* __restrict__ benc, const float* __restrict__ bdec,
                 float* __restrict__ C)
{
    __shared__ float As[BK][BM + 4];
    __shared__ float Bs[BK][BN + 4];

    int tid = threadIdx.x;
    int tx = tid & 15;     // n-direction
    int ty = tid >> 4;     // m-direction
    int m0 = blockIdx.y * BM;
    int n0 = blockIdx.x * BN;

    float total[8][8];
    #pragma unroll
    for (int i = 0; i < 8; i++)
        #pragma unroll
        for (int j = 0; j < 8; j++) total[i][j] = 0.f;

    for (int chunk = 0; chunk < NCHUNK; chunk++) {
        float acc[8][8];
        #pragma unroll
        for (int i = 0; i < 8; i++)
            #pragma unroll
            for (int j = 0; j < 8; j++) acc[i][j] = 0.f;

        for (int t = 0; t < KC / BK; t++) {
            int kt = chunk * KC + t * BK;
            #pragma unroll
            for (int ph = 0; ph < 2; ph++) {
                int fid = tid + ph * 256;       // 0..511
                int r   = fid >> 2;             // 0..127
                int c4  = (fid & 3) << 2;       // 0,4,8,12
                float4 av = *(const float4*)(X + (size_t)(m0 + r) * D_DIM + kt + c4);
                float4 bd = *(const float4*)(bdec + kt + c4);
                As[c4 + 0][r] = av.x - bd.x;
                As[c4 + 1][r] = av.y - bd.y;
                As[c4 + 2][r] = av.z - bd.z;
                As[c4 + 3][r] = av.w - bd.w;
                float4 bv = *(const float4*)(W + (size_t)(n0 + r) * D_DIM + kt + c4);
                Bs[c4 + 0][r] = bv.x;
                Bs[c4 + 1][r] = bv.y;
                Bs[c4 + 2][r] = bv.z;
                Bs[c4 + 3][r] = bv.w;
            }
            __syncthreads();
            #pragma unroll
            for (int kk = 0; kk < BK; kk++) {
                float a_f[8], b_f[8];
                *(float4*)&a_f[0] = *(float4*)&As[kk][ty * 8];
                *(float4*)&a_f[4] = *(float4*)&As[kk][ty * 8 + 4];
                *(float4*)&b_f[0] = *(float4*)&Bs[kk][tx * 8];
                *(float4*)&b_f[4] = *(float4*)&Bs[kk][tx * 8 + 4];
                #pragma unroll
                for (int i = 0; i < 8; i++)
                    #pragma unroll
                    for (int j = 0; j < 8; j++)
                        acc[i][j] += a_f[i] * b_f[j];
            }
            __syncthreads();
        }
        // panel combine: total = fl(total + P_chunk), left-to-right
        #pragma unroll
        for (int i = 0; i < 8; i++)
            #pragma unroll
            for (int j = 0; j < 8; j++) total[i][j] += acc[i][j];
    }

    float be[8];
    *(float4*)&be[0] = *(const float4*)(benc + n0 + tx * 8);
    *(float4*)&be[4] = *(const float4*)(benc + n0 + tx * 8 + 4);
    #pragma unroll
    for (int i = 0; i < 8; i++) {
        size_t row = (size_t)(m0 + ty * 8 + i);
        float4 v0, v1;
        v0.x = fmaxf(total[i][0] + be[0], 0.f);
        v0.y = fmaxf(total[i][1] + be[1], 0.f);
        v0.z = fmaxf(total[i][2] + be[2], 0.f);
        v0.w = fmaxf(total[i][3] + be[3], 0.f);
        v1.x = fmaxf(total[i][4] + be[4], 0.f);
        v1.y = fmaxf(total[i][5] + be[5], 0.f);
        v1.z = fmaxf(total[i][6] + be[6], 0.f);
        v1.w = fmaxf(total[i][7] + be[7], 0.f);
        *(float4*)(C + row * N_LAT + n0 + tx * 8)     = v0;
        *(float4*)(C + row * N_LAT + n0 + tx * 8 + 4) = v1;
    }
}

// ============================================================
// top-k per row: 3-level radix select on float bits (all >= 0),
// jax.lax.top_k semantics (desc value, asc index on ties)
// ============================================================
#define CAP_B 4096
#define TOPK_SMEM ((32768 + 2048 + CAP_B) * 4)

__global__ void topk_kernel(const float* __restrict__ feat,
                            float* __restrict__ p_ta, float* __restrict__ p_ti)
{
    extern __shared__ uint32_t dyn[];
    uint32_t* sv   = dyn;             // 32768
    uint32_t* hist = sv + 32768;      // 2048
    int*      listB = (int*)(hist + 2048); // CAP_B

    __shared__ int   csum[256];
    __shared__ int   red[256];
    __shared__ float pv[64];
    __shared__ int   pi[64];
    __shared__ int   listA[64];
    __shared__ int   tiesel[64];
    __shared__ uint32_t s_prefix;
    __shared__ int   s_kr, s_cntA, s_cntB, s_last;

    int tid = threadIdx.x;
    int row = blockIdx.x;

    const float4* src = (const float4*)(feat + (size_t)row * N_LAT);
    uint4* dst = (uint4*)sv;
    for (int i = tid; i < N_LAT / 4; i += 256) {
        float4 v = src[i];
        uint4 u;
        u.x = __float_as_uint(v.x); u.y = __float_as_uint(v.y);
        u.z = __float_as_uint(v.z); u.w = __float_as_uint(v.w);
        dst[i] = u;
    }
    __syncthreads();

    uint32_t prefix = 0;
    int Kr = TOPK;
    const int SH[3] = {21, 10, 0};
    const int NB[3] = {11, 11, 10};

    for (int lvl = 0; lvl < 3; lvl++) {
        int sh = SH[lvl], nbits = NB[lvl];
        int nbins = 1 << nbits;
        uint32_t mask = (uint32_t)(nbins - 1);
        int hib = sh + nbits;
        for (int i = tid; i < nbins; i += 256) hist[i] = 0;
        __syncthreads();
        int zloc = 0;
        for (int i = tid; i < N_LAT; i += 256) {
            uint32_t u = sv[i];
            bool match = (lvl == 0) || ((u >> hib) == prefix);
            if (match) {
                if (u == 0u) zloc++;
                else atomicAdd(&hist[(u >> sh) & mask], 1u);
            }
        }
        if (zloc) atomicAdd(&hist[0], (uint32_t)zloc);
        __syncthreads();
        int nch = nbins >> 3;
        if (tid < nch) {
            int s = 0;
            #pragma unroll
            for (int j = 0; j < 8; j++) s += (int)hist[tid * 8 + j];
            csum[tid] = s;
        }
        __syncthreads();
        if (tid == 0) {
            int acc = 0, c = nch - 1;
            for (; c > 0; c--) {
                if (acc + csum[c] >= Kr) break;
                acc += csum[c];
            }
            int b = c * 8 + 7;
            for (; b > c * 8; b--) {
                int h = (int)hist[b];
                if (acc + h >= Kr) break;
                acc += h;
            }
            s_prefix = (prefix << nbits) | (uint32_t)b;
            s_kr = Kr - acc;
        }
        __syncthreads();
        prefix = s_prefix;
        Kr = s_kr;
        __syncthreads();
    }

    uint32_t T = prefix;
    int Need = Kr;
    if (tid == 0) { s_cntA = 0; s_cntB = 0; }
    __syncthreads();
    for (int i = tid; i < N_LAT; i += 256) {
        uint32_t u = sv[i];
        if (u > T) {
            int p = atomicAdd(&s_cntA, 1);
            if (p < 64) listA[p] = i;
        } else if (u == T) {
            int p = atomicAdd(&s_cntB, 1);
            if (p < CAP_B) listB[p] = i;
        }
    }
    __syncthreads();
    int cA = s_cntA, cB = s_cntB;

    int last = -1;
    for (int s = 0; s < Need; s++) {
        int loc = 0x7FFFFFFF;
        if (cB <= CAP_B) {
            for (int i = tid; i < cB; i += 256) {
                int ix = listB[i];
                if (ix > last && ix < loc) loc = ix;
            }
        } else {
            for (int i = tid; i < N_LAT; i += 256) {
                if (sv[i] == T && i > last && i < loc) loc = i;
            }
        }
        red[tid] = loc;
        __syncthreads();
        for (int st = 128; st > 0; st >>= 1) {
            if (tid < st) red[tid] = min(red[tid], red[tid + st]);
            __syncthreads();
        }
        if (tid == 0) { tiesel[s] = red[0]; s_last = red[0]; }
        __syncthreads();
        last = s_last;
    }

    if (tid < 64) {
        float v; int ix;
        if (tid < cA) { ix = listA[tid]; v = __uint_as_float(sv[ix]); }
        else          { ix = tiesel[tid - cA]; v = __uint_as_float(T); }
        pv[tid] = v; pi[tid] = ix;
    }
    __syncthreads();
    if (tid < 64) {
        float v = pv[tid]; int ix = pi[tid];
        int rank = 0;
        #pragma unroll 8
        for (int j = 0; j < 64; j++) {
            float vj = pv[j]; int ij = pi[j];
            if (vj > v || (vj == v && ij < ix)) rank++;
        }
        size_t o = (size_t)row * TOPK + rank;
        g_top_val[o] = v;
        g_top_idx[o] = ix;
        if (p_ta) p_ta[o] = v;
        if (p_ti) p_ti[o] = (float)ix;
    }
}

// ============================================================
__global__ void decode_kernel(const float* __restrict__ X,
                              const float* __restrict__ Wd,
                              const float* __restrict__ bdec,
                              float* __restrict__ sae)
{
    __shared__ float sval[64];
    __shared__ int   sidx[64];
    __shared__ float red[256];
    int tid = threadIdx.x, row = blockIdx.x;
    if (tid < 64) {
        sval[tid] = g_top_val[row * TOPK + tid];
        sidx[tid] = g_top_idx[row * TOPK + tid];
    }
    __syncthreads();
    int d0 = tid * 4;
    float4 acc = *(const float4*)(bdec + d0);
    #pragma unroll 4
    for (int k = 0; k < TOPK; k++) {
        float a = sval[k];
        float4 w = *(const float4*)(Wd + (size_t)sidx[k] * D_DIM + d0);
        acc.x += a * w.x; acc.y += a * w.y; acc.z += a * w.z; acc.w += a * w.w;
    }
    size_t o = (size_t)row * D_DIM + d0;
    if (sae) *(float4*)(sae + o) = acc;
    float4 xv = *(const float4*)(X + o);
    float ex = acc.x - xv.x, ey = acc.y - xv.y, ez = acc.z - xv.z, ew = acc.w - xv.w;
    red[tid] = ex * ex + ey * ey + ez * ez + ew * ew;
    __syncthreads();
    for (int st = 128; st > 0; st >>= 1) {
        if (tid < st) red[tid] += red[tid + st];
        __syncthreads();
    }
    if (tid == 0) atomicAdd(&g_acc[0], red[0]);
}

// ============================================================
__global__ void finalize_kernel(float* __restrict__ p_sc) {
    __shared__ float red[256];
    int tid = threadIdx.x;
    float s = 0.f;
    for (int i = tid; i < D_DIM; i += 256) {
        float cs = g_colsum[i];
        s += cs * cs;
    }
    red[tid] = s;
    __syncthreads();
    for (int st = 128; st > 0; st >>= 1) {
        if (tid < st) red[tid] += red[tid + st];
        __syncthreads();
    }
    if (tid == 0) {
        float TV  = g_acc[1] - red[0] / (float)B_N;
        float SSE = g_acc[0];
        p_sc[0] = SSE / TV;
        p_sc[1] = 0.f;
        p_sc[2] = 0.f;
        p_sc[3] = 0.f;
        p_sc[4] = SSE / (float)B_N;
    }
}

// ============================================================
extern "C" void kernel_launch(void* const* d_in, const int* in_sizes, int n_in,
                              void* d_out, int out_size)
{
    const float *x = nullptr, *We = nullptr, *be = nullptr, *Wd = nullptr, *bd = nullptr;
    int big_seen = 0;
    for (int i = 0; i < n_in; i++) {
        int sz = in_sizes[i];
        const float* p = (const float*)d_in[i];
        if (sz == (int)SZ_SAE)          x = p;
        else if (sz == N_LAT * D_DIM)   { if (big_seen++ == 0) We = p; else Wd = p; }
        else if (sz == N_LAT)           be = p;
        else if (sz == D_DIM)           bd = p;
    }

    float* out = (float*)d_out;
    float *p_sae = nullptr, *p_feat = nullptr, *p_ta = nullptr, *p_ti = nullptr, *p_sc = nullptr;

    if ((size_t)out_size == TOTAL_FULL) {
        p_sae  = out;
        p_feat = out + SZ_SAE;
        p_ta   = out + SZ_SAE + SZ_FEAT;
        p_ti   = p_ta + SZ_TA;
        p_sc   = p_ti + SZ_TA;
    } else if ((size_t)out_size == TOTAL_NOFEAT) {
        p_sae = out;
        p_ta  = out + SZ_SAE;
        p_ti  = p_ta + SZ_TA;
        p_sc  = p_ti + SZ_TA;
    } else {
        p_sae = out;
    }

    if (!p_feat) {
        void* fp = nullptr;
        cudaGetSymbolAddress(&fp, g_feat_fallback);
        p_feat = (float*)fp;
    }

    init_kernel<<<1, 32>>>();
    colstats_kernel<<<D_DIM / 256, 256>>>(x);
    encode_gemm<<<dim3(N_LAT / BN, B_N / BM), 256>>>(x, We, be, bd, p_feat);
    cudaFuncSetAttribute(topk_kernel, cudaFuncAttributeMaxDynamicSharedMemorySize, TOPK_SMEM);
    topk_kernel<<<B_N, 256, TOPK_SMEM>>>(p_feat, p_ta, p_ti);
    decode_kernel<<<B_N, 256>>>(x, Wd, bd, p_sae);
    if (p_sc) finalize_kernel<<<1, 256>>>(p_sc);
}

// round 7
// speedup vs baseline: 1.0301x; 1.0301x over previous
#include <cuda_runtime.h>
#include <cstdint>

#define B_N   4096
#define D_DIM 1024
#define N_LAT 32768
#define TOPK  64

// frozen arithmetic: 2 k-panels of 512, fresh acc, fl(P0+P1), +b_enc, relu
#define KC 512
#define NT 64                 // k-tiles of 16
#define TILES_PER_CHUNK 32    // 512/16

// ---- output layout (flattened tuple concat, f32) ----
#define SZ_SAE  ((size_t)B_N * D_DIM)
#define SZ_FEAT ((size_t)B_N * N_LAT)
#define SZ_TA   ((size_t)B_N * TOPK)
#define TOTAL_FULL (SZ_SAE + SZ_FEAT + SZ_TA + SZ_TA + 5)
#define TOTAL_NOFEAT (SZ_SAE + SZ_TA + SZ_TA + 5)

// ---- scratch ----
__device__ float g_top_val[B_N * TOPK];
__device__ int   g_top_idx[B_N * TOPK];
__device__ float g_colsum[D_DIM];
__device__ float g_acc[4];
__device__ float g_xc[(size_t)B_N * D_DIM];          // x - b_dec
__device__ float g_feat_fallback[(size_t)B_N * N_LAT];

#define FMA2(c,a,b) asm("fma.rn.f32x2 %0, %1, %2, %3;" : "=l"(c) : "l"(a), "l"(b), "l"(c))
#define ADD2(c,a,b) asm("add.rn.f32x2 %0, %1, %2;"     : "=l"(c) : "l"(a), "l"(b))

__device__ __forceinline__ float f2lo(unsigned long long v) { return __uint_as_float((unsigned)v); }
__device__ __forceinline__ float f2hi(unsigned long long v) { return __uint_as_float((unsigned)(v >> 32)); }
__device__ __forceinline__ unsigned long long fdup(float f) {
    unsigned u = __float_as_uint(f);
    return ((unsigned long long)u << 32) | u;
}

// ============================================================
__global__ void init_kernel() {
    int t = threadIdx.x;
    if (t < 4) g_acc[t] = 0.0f;
}

// xc = x - b_dec (elementwise, same fl as reference)
__global__ void xc_kernel(const float* __restrict__ X, const float* __restrict__ bdec) {
    int i = blockIdx.x * blockDim.x + threadIdx.x;      // float4 index
    float4 v = ((const float4*)X)[i];
    float4 d = ((const float4*)bdec)[i & 255];
    v.x -= d.x; v.y -= d.y; v.z -= d.z; v.w -= d.w;
    ((float4*)g_xc)[i] = v;
}

// ============================================================
__global__ void colstats_kernel(const float* __restrict__ X) {
    int c = blockIdx.x * blockDim.x + threadIdx.x;
    float s = 0.f, q = 0.f;
    #pragma unroll 4
    for (int n = 0; n < B_N; n++) {
        float v = X[(size_t)n * D_DIM + c];
        s += v;
        q += v * v;
    }
    g_colsum[c] = s;
    atomicAdd(&g_acc[1], q);
}

// ============================================================
// encode GEMM, FFMA2 version.
// 128x128 tile, 512 threads, 8m x 4n per thread (n packed in f32x2 pairs).
// A staged in smem as duplicated (a,a) 64-bit pairs; B natural pairs.
// 2-stage reg-staged double buffering. k-order per element preserved exactly.
// ============================================================
__global__ __launch_bounds__(512, 1)
void encode_gemm(const float* __restrict__ W,
                 const float* __restrict__ benc,
                 float* __restrict__ C)
{
    __shared__ unsigned long long As2[2][16][128];   // 32 KB: (a,a) pairs, [k][m]
    __shared__ float              Bs [2][16][128];   // 16 KB: [k][n]

    int tid = threadIdx.x;
    int tx  = tid & 31;          // n group: cols tx*4..tx*4+3
    int ty  = tid >> 5;          // m group: rows ty*8..ty*8+7
    int ty8 = ty * 8;
    int tx4 = tx * 4;
    int m0 = blockIdx.x * 128;   // x = m (fast) for W-panel L2 reuse within wave
    int n0 = blockIdx.y * 128;

    int lr = tid >> 2;           // 0..127 loader row
    int lc = (tid & 3) << 2;     // 0,4,8,12 loader k-offset

    const float* aptr = g_xc + (size_t)(m0 + lr) * D_DIM + lc;
    const float* bptr = W    + (size_t)(n0 + lr) * D_DIM + lc;

    float4 ra, rb;               // staging registers

    // prologue: tile 0 -> stage 0
    ra = *(const float4*)(aptr);
    rb = *(const float4*)(bptr);
    As2[0][lc + 0][lr] = fdup(ra.x);
    As2[0][lc + 1][lr] = fdup(ra.y);
    As2[0][lc + 2][lr] = fdup(ra.z);
    As2[0][lc + 3][lr] = fdup(ra.w);
    Bs [0][lc + 0][lr] = rb.x;
    Bs [0][lc + 1][lr] = rb.y;
    Bs [0][lc + 2][lr] = rb.z;
    Bs [0][lc + 3][lr] = rb.w;
    // prefetch tile 1
    ra = *(const float4*)(aptr + 16);
    rb = *(const float4*)(bptr + 16);
    __syncthreads();

    unsigned long long acc[8][2], tot[8][2];
    #pragma unroll
    for (int i = 0; i < 8; i++) { acc[i][0] = 0ULL; acc[i][1] = 0ULL; }

    for (int t = 0; t < NT; t++) {
        int s = t & 1;
        #pragma unroll
        for (int kk = 0; kk < 16; kk++) {
            const ulonglong2* ap = (const ulonglong2*)&As2[s][kk][ty8];
            const ulonglong2* bp = (const ulonglong2*)&Bs [s][kk][tx4];
            ulonglong2 bv = bp[0];                  // (b0,b1),(b2,b3)
            ulonglong2 a01 = ap[0], a23 = ap[1], a45 = ap[2], a67 = ap[3];
            FMA2(acc[0][0], a01.x, bv.x); FMA2(acc[0][1], a01.x, bv.y);
            FMA2(acc[1][0], a01.y, bv.x); FMA2(acc[1][1], a01.y, bv.y);
            FMA2(acc[2][0], a23.x, bv.x); FMA2(acc[2][1], a23.x, bv.y);
            FMA2(acc[3][0], a23.y, bv.x); FMA2(acc[3][1], a23.y, bv.y);
            FMA2(acc[4][0], a45.x, bv.x); FMA2(acc[4][1], a45.x, bv.y);
            FMA2(acc[5][0], a45.y, bv.x); FMA2(acc[5][1], a45.y, bv.y);
            FMA2(acc[6][0], a67.x, bv.x); FMA2(acc[6][1], a67.x, bv.y);
            FMA2(acc[7][0], a67.y, bv.x); FMA2(acc[7][1], a67.y, bv.y);
        }

        // chunk boundary: P0 done -> move to tot (exact), restart acc
        if (t == TILES_PER_CHUNK - 1) {
            #pragma unroll
            for (int i = 0; i < 8; i++) {
                tot[i][0] = acc[i][0]; tot[i][1] = acc[i][1];
                acc[i][0] = 0ULL;      acc[i][1] = 0ULL;
            }
        }

        if (t < NT - 1) {
            int sn = (t + 1) & 1;
            As2[sn][lc + 0][lr] = fdup(ra.x);
            As2[sn][lc + 1][lr] = fdup(ra.y);
            As2[sn][lc + 2][lr] = fdup(ra.z);
            As2[sn][lc + 3][lr] = fdup(ra.w);
            Bs [sn][lc + 0][lr] = rb.x;
            Bs [sn][lc + 1][lr] = rb.y;
            Bs [sn][lc + 2][lr] = rb.z;
            Bs [sn][lc + 3][lr] = rb.w;
            if (t < NT - 2) {
                ra = *(const float4*)(aptr + (t + 2) * 16);
                rb = *(const float4*)(bptr + (t + 2) * 16);
            }
        }
        __syncthreads();
    }

    // tot = fl(P0 + P1), lanewise rn adds == scalar
    #pragma unroll
    for (int i = 0; i < 8; i++) {
        ADD2(tot[i][0], tot[i][0], acc[i][0]);
        ADD2(tot[i][1], tot[i][1], acc[i][1]);
    }

    float4 bev = *(const float4*)(benc + n0 + tx4);
    #pragma unroll
    for (int i = 0; i < 8; i++) {
        size_t row = (size_t)(m0 + ty8 + i);
        float4 o;
        o.x = fmaxf(f2lo(tot[i][0]) + bev.x, 0.f);
        o.y = fmaxf(f2hi(tot[i][0]) + bev.y, 0.f);
        o.z = fmaxf(f2lo(tot[i][1]) + bev.z, 0.f);
        o.w = fmaxf(f2hi(tot[i][1]) + bev.w, 0.f);
        *(float4*)(C + row * N_LAT + n0 + tx4) = o;
    }
}

// ============================================================
// top-k per row (unchanged, passing)
// ============================================================
#define CAP_B 4096
#define TOPK_SMEM ((32768 + 2048 + CAP_B) * 4)

__global__ void topk_kernel(const float* __restrict__ feat,
                            float* __restrict__ p_ta, float* __restrict__ p_ti)
{
    extern __shared__ uint32_t dyn[];
    uint32_t* sv   = dyn;
    uint32_t* hist = sv + 32768;
    int*      listB = (int*)(hist + 2048);

    __shared__ int   csum[256];
    __shared__ int   red[256];
    __shared__ float pv[64];
    __shared__ int   pi[64];
    __shared__ int   listA[64];
    __shared__ int   tiesel[64];
    __shared__ uint32_t s_prefix;
    __shared__ int   s_kr, s_cntA, s_cntB, s_last;

    int tid = threadIdx.x;
    int row = blockIdx.x;

    const float4* src = (const float4*)(feat + (size_t)row * N_LAT);
    uint4* dst = (uint4*)sv;
    for (int i = tid; i < N_LAT / 4; i += 256) {
        float4 v = src[i];
        uint4 u;
        u.x = __float_as_uint(v.x); u.y = __float_as_uint(v.y);
        u.z = __float_as_uint(v.z); u.w = __float_as_uint(v.w);
        dst[i] = u;
    }
    __syncthreads();

    uint32_t prefix = 0;
    int Kr = TOPK;
    const int SH[3] = {21, 10, 0};
    const int NB[3] = {11, 11, 10};

    for (int lvl = 0; lvl < 3; lvl++) {
        int sh = SH[lvl], nbits = NB[lvl];
        int nbins = 1 << nbits;
        uint32_t mask = (uint32_t)(nbins - 1);
        int hib = sh + nbits;
        for (int i = tid; i < nbins; i += 256) hist[i] = 0;
        __syncthreads();
        int zloc = 0;
        for (int i = tid; i < N_LAT; i += 256) {
            uint32_t u = sv[i];
            bool match = (lvl == 0) || ((u >> hib) == prefix);
            if (match) {
                if (u == 0u) zloc++;
                else atomicAdd(&hist[(u >> sh) & mask], 1u);
            }
        }
        if (zloc) atomicAdd(&hist[0], (uint32_t)zloc);
        __syncthreads();
        int nch = nbins >> 3;
        if (tid < nch) {
            int s = 0;
            #pragma unroll
            for (int j = 0; j < 8; j++) s += (int)hist[tid * 8 + j];
            csum[tid] = s;
        }
        __syncthreads();
        if (tid == 0) {
            int acc = 0, c = nch - 1;
            for (; c > 0; c--) {
                if (acc + csum[c] >= Kr) break;
                acc += csum[c];
            }
            int b = c * 8 + 7;
            for (; b > c * 8; b--) {
                int h = (int)hist[b];
                if (acc + h >= Kr) break;
                acc += h;
            }
            s_prefix = (prefix << nbits) | (uint32_t)b;
            s_kr = Kr - acc;
        }
        __syncthreads();
        prefix = s_prefix;
        Kr = s_kr;
        __syncthreads();
    }

    uint32_t T = prefix;
    int Need = Kr;
    if (tid == 0) { s_cntA = 0; s_cntB = 0; }
    __syncthreads();
    for (int i = tid; i < N_LAT; i += 256) {
        uint32_t u = sv[i];
        if (u > T) {
            int p = atomicAdd(&s_cntA, 1);
            if (p < 64) listA[p] = i;
        } else if (u == T) {
            int p = atomicAdd(&s_cntB, 1);
            if (p < CAP_B) listB[p] = i;
        }
    }
    __syncthreads();
    int cA = s_cntA, cB = s_cntB;

    int last = -1;
    for (int s = 0; s < Need; s++) {
        int loc = 0x7FFFFFFF;
        if (cB <= CAP_B) {
            for (int i = tid; i < cB; i += 256) {
                int ix = listB[i];
                if (ix > last && ix < loc) loc = ix;
            }
        } else {
            for (int i = tid; i < N_LAT; i += 256) {
                if (sv[i] == T && i > last && i < loc) loc = i;
            }
        }
        red[tid] = loc;
        __syncthreads();
        for (int st = 128; st > 0; st >>= 1) {
            if (tid < st) red[tid] = min(red[tid], red[tid + st]);
            __syncthreads();
        }
        if (tid == 0) { tiesel[s] = red[0]; s_last = red[0]; }
        __syncthreads();
        last = s_last;
    }

    if (tid < 64) {
        float v; int ix;
        if (tid < cA) { ix = listA[tid]; v = __uint_as_float(sv[ix]); }
        else          { ix = tiesel[tid - cA]; v = __uint_as_float(T); }
        pv[tid] = v; pi[tid] = ix;
    }
    __syncthreads();
    if (tid < 64) {
        float v = pv[tid]; int ix = pi[tid];
        int rank = 0;
        #pragma unroll 8
        for (int j = 0; j < 64; j++) {
            float vj = pv[j]; int ij = pi[j];
            if (vj > v || (vj == v && ij < ix)) rank++;
        }
        size_t o = (size_t)row * TOPK + rank;
        g_top_val[o] = v;
        g_top_idx[o] = ix;
        if (p_ta) p_ta[o] = v;
        if (p_ti) p_ti[o] = (float)ix;
    }
}

// ============================================================
__global__ void decode_kernel(const float* __restrict__ X,
                              const float* __restrict__ Wd,
                              const float* __restrict__ bdec,
                              float* __restrict__ sae)
{
    __shared__ float sval[64];
    __shared__ int   sidx[64];
    __shared__ float red[256];
    int tid = threadIdx.x, row = blockIdx.x;
    if (tid < 64) {
        sval[tid] = g_top_val[row * TOPK + tid];
        sidx[tid] = g_top_idx[row * TOPK + tid];
    }
    __syncthreads();
    int d0 = tid * 4;
    float4 acc = *(const float4*)(bdec + d0);
    #pragma unroll 4
    for (int k = 0; k < TOPK; k++) {
        float a = sval[k];
        float4 w = *(const float4*)(Wd + (size_t)sidx[k] * D_DIM + d0);
        acc.x += a * w.x; acc.y += a * w.y; acc.z += a * w.z; acc.w += a * w.w;
    }
    size_t o = (size_t)row * D_DIM + d0;
    if (sae) *(float4*)(sae + o) = acc;
    float4 xv = *(const float4*)(X + o);
    float ex = acc.x - xv.x, ey = acc.y - xv.y, ez = acc.z - xv.z, ew = acc.w - xv.w;
    red[tid] = ex * ex + ey * ey + ez * ez + ew * ew;
    __syncthreads();
    for (int st = 128; st > 0; st >>= 1) {
        if (tid < st) red[tid] += red[tid + st];
        __syncthreads();
    }
    if (tid == 0) atomicAdd(&g_acc[0], red[0]);
}

// ============================================================
__global__ void finalize_kernel(float* __restrict__ p_sc) {
    __shared__ float red[256];
    int tid = threadIdx.x;
    float s = 0.f;
    for (int i = tid; i < D_DIM; i += 256) {
        float cs = g_colsum[i];
        s += cs * cs;
    }
    red[tid] = s;
    __syncthreads();
    for (int st = 128; st > 0; st >>= 1) {
        if (tid < st) red[tid] += red[tid + st];
        __syncthreads();
    }
    if (tid == 0) {
        float TV  = g_acc[1] - red[0] / (float)B_N;
        float SSE = g_acc[0];
        p_sc[0] = SSE / TV;
        p_sc[1] = 0.f;
        p_sc[2] = 0.f;
        p_sc[3] = 0.f;
        p_sc[4] = SSE / (float)B_N;
    }
}

// ============================================================
extern "C" void kernel_launch(void* const* d_in, const int* in_sizes, int n_in,
                              void* d_out, int out_size)
{
    const float *x = nullptr, *We = nullptr, *be = nullptr, *Wd = nullptr, *bd = nullptr;
    int big_seen = 0;
    for (int i = 0; i < n_in; i++) {
        int sz = in_sizes[i];
        const float* p = (const float*)d_in[i];
        if (sz == (int)SZ_SAE)          x = p;
        else if (sz == N_LAT * D_DIM)   { if (big_seen++ == 0) We = p; else Wd = p; }
        else if (sz == N_LAT)           be = p;
        else if (sz == D_DIM)           bd = p;
    }

    float* out = (float*)d_out;
    float *p_sae = nullptr, *p_feat = nullptr, *p_ta = nullptr, *p_ti = nullptr, *p_sc = nullptr;

    if ((size_t)out_size == TOTAL_FULL) {
        p_sae  = out;
        p_feat = out + SZ_SAE;
        p_ta   = out + SZ_SAE + SZ_FEAT;
        p_ti   = p_ta + SZ_TA;
        p_sc   = p_ti + SZ_TA;
    } else if ((size_t)out_size == TOTAL_NOFEAT) {
        p_sae = out;
        p_ta  = out + SZ_SAE;
        p_ti  = p_ta + SZ_TA;
        p_sc  = p_ti + SZ_TA;
    } else {
        p_sae = out;
    }

    if (!p_feat) {
        void* fp = nullptr;
        cudaGetSymbolAddress(&fp, g_feat_fallback);
        p_feat = (float*)fp;
    }

    init_kernel<<<1, 32>>>();
    xc_kernel<<<(B_N * D_DIM / 4) / 256, 256>>>(x, bd);
    colstats_kernel<<<D_DIM / 256, 256>>>(x);
    encode_gemm<<<dim3(B_N / 128, N_LAT / 128), 512>>>(We, be, p_feat);
    cudaFuncSetAttribute(topk_kernel, cudaFuncAttributeMaxDynamicSharedMemorySize, TOPK_SMEM);
    topk_kernel<<<B_N, 256, TOPK_SMEM>>>(p_feat, p_ta, p_ti);
    decode_kernel<<<B_N, 256>>>(x, Wd, bd, p_sae);
    if (p_sc) finalize_kernel<<<1, 256>>>(p_sc);
}

// round 8
// speedup vs baseline: 1.0316x; 1.0014x over previous
#include <cuda_runtime.h>
#include <cstdint>

#define B_N   4096
#define D_DIM 1024
#define N_LAT 32768
#define TOPK  64

// frozen arithmetic: 2 k-panels of 512, fresh acc, fl(P0+P1), +b_enc, relu
#define NT 64                 // k-tiles of 16
#define TILES_PER_CHUNK 32    // 512/16

// ---- output layout (flattened tuple concat, f32) ----
#define SZ_SAE  ((size_t)B_N * D_DIM)
#define SZ_FEAT ((size_t)B_N * N_LAT)
#define SZ_TA   ((size_t)B_N * TOPK)
#define TOTAL_FULL (SZ_SAE + SZ_FEAT + SZ_TA + SZ_TA + 5)
#define TOTAL_NOFEAT (SZ_SAE + SZ_TA + SZ_TA + 5)

// ---- scratch ----
__device__ float g_top_val[B_N * TOPK];
__device__ int   g_top_idx[B_N * TOPK];
__device__ float g_colsum[D_DIM];
__device__ float g_acc[4];
__device__ float g_xc[(size_t)B_N * D_DIM];          // x - b_dec
__device__ float g_feat_fallback[(size_t)B_N * N_LAT];

#define FMA2(c,a,b) asm("fma.rn.f32x2 %0, %1, %2, %3;" : "=l"(c) : "l"(a), "l"(b), "l"(c))
#define ADD2(c,a,b) asm("add.rn.f32x2 %0, %1, %2;"     : "=l"(c) : "l"(a), "l"(b))

__device__ __forceinline__ float f2lo(unsigned long long v) { return __uint_as_float((unsigned)v); }
__device__ __forceinline__ float f2hi(unsigned long long v) { return __uint_as_float((unsigned)(v >> 32)); }
__device__ __forceinline__ unsigned long long fdup(float f) {
    unsigned u = __float_as_uint(f);
    return ((unsigned long long)u << 32) | u;
}

// ============================================================
__global__ void init_kernel() {
    int t = threadIdx.x;
    if (t < 4) g_acc[t] = 0.0f;
}

// xc = x - b_dec (elementwise, same fl as reference)
__global__ void xc_kernel(const float* __restrict__ X, const float* __restrict__ bdec) {
    int i = blockIdx.x * blockDim.x + threadIdx.x;      // float4 index
    float4 v = ((const float4*)X)[i];
    float4 d = ((const float4*)bdec)[i & 255];
    v.x -= d.x; v.y -= d.y; v.z -= d.z; v.w -= d.w;
    ((float4*)g_xc)[i] = v;
}

// ============================================================
__global__ void colstats_kernel(const float* __restrict__ X) {
    int c = blockIdx.x * blockDim.x + threadIdx.x;
    float s = 0.f, q = 0.f;
    #pragma unroll 4
    for (int n = 0; n < B_N; n++) {
        float v = X[(size_t)n * D_DIM + c];
        s += v;
        q += v * v;
    }
    g_colsum[c] = s;
    atomicAdd(&g_acc[1], q);
}

// ============================================================
// encode GEMM, FFMA2, 256 threads, 8m x 8n per thread.
// A in smem as duplicated (a,a) 64-bit pairs [k][m]; B natural floats [k][n].
// 2-stage double buffering. Per-element k-order preserved exactly.
// ============================================================
__global__ __launch_bounds__(256, 1)
void encode_gemm(const float* __restrict__ W,
                 const float* __restrict__ benc,
                 float* __restrict__ C)
{
    __shared__ unsigned long long As2[2][16][128];   // 32 KB
    __shared__ float              Bs [2][16][128];   // 16 KB

    int tid = threadIdx.x;
    int tx  = tid & 15;          // n group: cols tx*8..tx*8+7
    int ty  = tid >> 4;          // m group: rows ty*8..ty*8+7
    int ty8 = ty * 8;
    int tx8 = tx * 8;
    int m0 = blockIdx.x * 128;
    int n0 = blockIdx.y * 128;

    int lr = tid >> 1;           // 0..127 loader row
    int lc = (tid & 1) << 3;     // 0 or 8 loader k-offset

    const float* aptr = g_xc + (size_t)(m0 + lr) * D_DIM + lc;
    const float* bptr = W    + (size_t)(n0 + lr) * D_DIM + lc;

    float4 ra0, ra1, rb0, rb1;   // staging registers (8 floats each of A,B)

    // prologue: tile 0 -> stage 0
    ra0 = *(const float4*)(aptr);
    ra1 = *(const float4*)(aptr + 4);
    rb0 = *(const float4*)(bptr);
    rb1 = *(const float4*)(bptr + 4);
    As2[0][lc + 0][lr] = fdup(ra0.x);
    As2[0][lc + 1][lr] = fdup(ra0.y);
    As2[0][lc + 2][lr] = fdup(ra0.z);
    As2[0][lc + 3][lr] = fdup(ra0.w);
    As2[0][lc + 4][lr] = fdup(ra1.x);
    As2[0][lc + 5][lr] = fdup(ra1.y);
    As2[0][lc + 6][lr] = fdup(ra1.z);
    As2[0][lc + 7][lr] = fdup(ra1.w);
    Bs [0][lc + 0][lr] = rb0.x;
    Bs [0][lc + 1][lr] = rb0.y;
    Bs [0][lc + 2][lr] = rb0.z;
    Bs [0][lc + 3][lr] = rb0.w;
    Bs [0][lc + 4][lr] = rb1.x;
    Bs [0][lc + 5][lr] = rb1.y;
    Bs [0][lc + 6][lr] = rb1.z;
    Bs [0][lc + 7][lr] = rb1.w;
    // prefetch tile 1
    ra0 = *(const float4*)(aptr + 16);
    ra1 = *(const float4*)(aptr + 20);
    rb0 = *(const float4*)(bptr + 16);
    rb1 = *(const float4*)(bptr + 20);
    __syncthreads();

    unsigned long long acc[8][4], tot[8][4];
    #pragma unroll
    for (int i = 0; i < 8; i++)
        #pragma unroll
        for (int j = 0; j < 4; j++) acc[i][j] = 0ULL;

    for (int t = 0; t < NT; t++) {
        int s = t & 1;
        #pragma unroll
        for (int kk = 0; kk < 16; kk++) {
            const ulonglong2* ap = (const ulonglong2*)&As2[s][kk][ty8];
            const ulonglong2* bp = (const ulonglong2*)&Bs [s][kk][tx8];
            ulonglong2 b01_23 = bp[0];               // (b0,b1),(b2,b3)
            ulonglong2 b45_67 = bp[1];               // (b4,b5),(b6,b7)
            ulonglong2 a01 = ap[0], a23 = ap[1], a45 = ap[2], a67 = ap[3];
            #pragma unroll
            for (int i = 0; i < 8; i++) {
                unsigned long long av =
                    (i < 2) ? ((i & 1) ? a01.y : a01.x) :
                    (i < 4) ? ((i & 1) ? a23.y : a23.x) :
                    (i < 6) ? ((i & 1) ? a45.y : a45.x) :
                              ((i & 1) ? a67.y : a67.x);
                FMA2(acc[i][0], av, b01_23.x);
                FMA2(acc[i][1], av, b01_23.y);
                FMA2(acc[i][2], av, b45_67.x);
                FMA2(acc[i][3], av, b45_67.y);
            }
        }

        // chunk boundary: P0 done -> move to tot (exact), restart acc
        if (t == TILES_PER_CHUNK - 1) {
            #pragma unroll
            for (int i = 0; i < 8; i++)
                #pragma unroll
                for (int j = 0; j < 4; j++) {
                    tot[i][j] = acc[i][j];
                    acc[i][j] = 0ULL;
                }
        }

        if (t < NT - 1) {
            int sn = (t + 1) & 1;
            As2[sn][lc + 0][lr] = fdup(ra0.x);
            As2[sn][lc + 1][lr] = fdup(ra0.y);
            As2[sn][lc + 2][lr] = fdup(ra0.z);
            As2[sn][lc + 3][lr] = fdup(ra0.w);
            As2[sn][lc + 4][lr] = fdup(ra1.x);
            As2[sn][lc + 5][lr] = fdup(ra1.y);
            As2[sn][lc + 6][lr] = fdup(ra1.z);
            As2[sn][lc + 7][lr] = fdup(ra1.w);
            Bs [sn][lc + 0][lr] = rb0.x;
            Bs [sn][lc + 1][lr] = rb0.y;
            Bs [sn][lc + 2][lr] = rb0.z;
            Bs [sn][lc + 3][lr] = rb0.w;
            Bs [sn][lc + 4][lr] = rb1.x;
            Bs [sn][lc + 5][lr] = rb1.y;
            Bs [sn][lc + 6][lr] = rb1.z;
            Bs [sn][lc + 7][lr] = rb1.w;
            if (t < NT - 2) {
                ra0 = *(const float4*)(aptr + (t + 2) * 16);
                ra1 = *(const float4*)(aptr + (t + 2) * 16 + 4);
                rb0 = *(const float4*)(bptr + (t + 2) * 16);
                rb1 = *(const float4*)(bptr + (t + 2) * 16 + 4);
            }
        }
        __syncthreads();
    }

    // tot = fl(P0 + P1), lanewise rn adds == scalar
    #pragma unroll
    for (int i = 0; i < 8; i++)
        #pragma unroll
        for (int j = 0; j < 4; j++)
            ADD2(tot[i][j], tot[i][j], acc[i][j]);

    float4 bev0 = *(const float4*)(benc + n0 + tx8);
    float4 bev1 = *(const float4*)(benc + n0 + tx8 + 4);
    #pragma unroll
    for (int i = 0; i < 8; i++) {
        size_t row = (size_t)(m0 + ty8 + i);
        float4 o0, o1;
        o0.x = fmaxf(f2lo(tot[i][0]) + bev0.x, 0.f);
        o0.y = fmaxf(f2hi(tot[i][0]) + bev0.y, 0.f);
        o0.z = fmaxf(f2lo(tot[i][1]) + bev0.z, 0.f);
        o0.w = fmaxf(f2hi(tot[i][1]) + bev0.w, 0.f);
        o1.x = fmaxf(f2lo(tot[i][2]) + bev1.x, 0.f);
        o1.y = fmaxf(f2hi(tot[i][2]) + bev1.y, 0.f);
        o1.z = fmaxf(f2lo(tot[i][3]) + bev1.z, 0.f);
        o1.w = fmaxf(f2hi(tot[i][3]) + bev1.w, 0.f);
        *(float4*)(C + row * N_LAT + n0 + tx8)     = o0;
        *(float4*)(C + row * N_LAT + n0 + tx8 + 4) = o1;
    }
}

// ============================================================
// top-k per row (unchanged, passing)
// ============================================================
#define CAP_B 4096
#define TOPK_SMEM ((32768 + 2048 + CAP_B) * 4)

__global__ void topk_kernel(const float* __restrict__ feat,
                            float* __restrict__ p_ta, float* __restrict__ p_ti)
{
    extern __shared__ uint32_t dyn[];
    uint32_t* sv   = dyn;
    uint32_t* hist = sv + 32768;
    int*      listB = (int*)(hist + 2048);

    __shared__ int   csum[256];
    __shared__ int   red[256];
    __shared__ float pv[64];
    __shared__ int   pi[64];
    __shared__ int   listA[64];
    __shared__ int   tiesel[64];
    __shared__ uint32_t s_prefix;
    __shared__ int   s_kr, s_cntA, s_cntB, s_last;

    int tid = threadIdx.x;
    int row = blockIdx.x;

    const float4* src = (const float4*)(feat + (size_t)row * N_LAT);
    uint4* dst = (uint4*)sv;
    for (int i = tid; i < N_LAT / 4; i += 256) {
        float4 v = src[i];
        uint4 u;
        u.x = __float_as_uint(v.x); u.y = __float_as_uint(v.y);
        u.z = __float_as_uint(v.z); u.w = __float_as_uint(v.w);
        dst[i] = u;
    }
    __syncthreads();

    uint32_t prefix = 0;
    int Kr = TOPK;
    const int SH[3] = {21, 10, 0};
    const int NB[3] = {11, 11, 10};

    for (int lvl = 0; lvl < 3; lvl++) {
        int sh = SH[lvl], nbits = NB[lvl];
        int nbins = 1 << nbits;
        uint32_t mask = (uint32_t)(nbins - 1);
        int hib = sh + nbits;
        for (int i = tid; i < nbins; i += 256) hist[i] = 0;
        __syncthreads();
        int zloc = 0;
        for (int i = tid; i < N_LAT; i += 256) {
            uint32_t u = sv[i];
            bool match = (lvl == 0) || ((u >> hib) == prefix);
            if (match) {
                if (u == 0u) zloc++;
                else atomicAdd(&hist[(u >> sh) & mask], 1u);
            }
        }
        if (zloc) atomicAdd(&hist[0], (uint32_t)zloc);
        __syncthreads();
        int nch = nbins >> 3;
        if (tid < nch) {
            int s = 0;
            #pragma unroll
            for (int j = 0; j < 8; j++) s += (int)hist[tid * 8 + j];
            csum[tid] = s;
        }
        __syncthreads();
        if (tid == 0) {
            int acc = 0, c = nch - 1;
            for (; c > 0; c--) {
                if (acc + csum[c] >= Kr) break;
                acc += csum[c];
            }
            int b = c * 8 + 7;
            for (; b > c * 8; b--) {
                int h = (int)hist[b];
                if (acc + h >= Kr) break;
                acc += h;
            }
            s_prefix = (prefix << nbits) | (uint32_t)b;
            s_kr = Kr - acc;
        }
        __syncthreads();
        prefix = s_prefix;
        Kr = s_kr;
        __syncthreads();
    }

    uint32_t T = prefix;
    int Need = Kr;
    if (tid == 0) { s_cntA = 0; s_cntB = 0; }
    __syncthreads();
    for (int i = tid; i < N_LAT; i += 256) {
        uint32_t u = sv[i];
        if (u > T) {
            int p = atomicAdd(&s_cntA, 1);
            if (p < 64) listA[p] = i;
        } else if (u == T) {
            int p = atomicAdd(&s_cntB, 1);
            if (p < CAP_B) listB[p] = i;
        }
    }
    __syncthreads();
    int cA = s_cntA, cB = s_cntB;

    int last = -1;
    for (int s = 0; s < Need; s++) {
        int loc = 0x7FFFFFFF;
        if (cB <= CAP_B) {
            for (int i = tid; i < cB; i += 256) {
                int ix = listB[i];
                if (ix > last && ix < loc) loc = ix;
            }
        } else {
            for (int i = tid; i < N_LAT; i += 256) {
                if (sv[i] == T && i > last && i < loc) loc = i;
            }
        }
        red[tid] = loc;
        __syncthreads();
        for (int st = 128; st > 0; st >>= 1) {
            if (tid < st) red[tid] = min(red[tid], red[tid + st]);
            __syncthreads();
        }
        if (tid == 0) { tiesel[s] = red[0]; s_last = red[0]; }
        __syncthreads();
        last = s_last;
    }

    if (tid < 64) {
        float v; int ix;
        if (tid < cA) { ix = listA[tid]; v = __uint_as_float(sv[ix]); }
        else          { ix = tiesel[tid - cA]; v = __uint_as_float(T); }
        pv[tid] = v; pi[tid] = ix;
    }
    __syncthreads();
    if (tid < 64) {
        float v = pv[tid]; int ix = pi[tid];
        int rank = 0;
        #pragma unroll 8
        for (int j = 0; j < 64; j++) {
            float vj = pv[j]; int ij = pi[j];
            if (vj > v || (vj == v && ij < ix)) rank++;
        }
        size_t o = (size_t)row * TOPK + rank;
        g_top_val[o] = v;
        g_top_idx[o] = ix;
        if (p_ta) p_ta[o] = v;
        if (p_ti) p_ti[o] = (float)ix;
    }
}

// ============================================================
__global__ void decode_kernel(const float* __restrict__ X,
                              const float* __restrict__ Wd,
                              const float* __restrict__ bdec,
                              float* __restrict__ sae)
{
    __shared__ float sval[64];
    __shared__ int   sidx[64];
    __shared__ float red[256];
    int tid = threadIdx.x, row = blockIdx.x;
    if (tid < 64) {
        sval[tid] = g_top_val[row * TOPK + tid];
        sidx[tid] = g_top_idx[row * TOPK + tid];
    }
    __syncthreads();
    int d0 = tid * 4;
    float4 acc = *(const float4*)(bdec + d0);
    #pragma unroll 4
    for (int k = 0; k < TOPK; k++) {
        float a = sval[k];
        float4 w = *(const float4*)(Wd + (size_t)sidx[k] * D_DIM + d0);
        acc.x += a * w.x; acc.y += a * w.y; acc.z += a * w.z; acc.w += a * w.w;
    }
    size_t o = (size_t)row * D_DIM + d0;
    if (sae) *(float4*)(sae + o) = acc;
    float4 xv = *(const float4*)(X + o);
    float ex = acc.x - xv.x, ey = acc.y - xv.y, ez = acc.z - xv.z, ew = acc.w - xv.w;
    red[tid] = ex * ex + ey * ey + ez * ez + ew * ew;
    __syncthreads();
    for (int st = 128; st > 0; st >>= 1) {
        if (tid < st) red[tid] += red[tid + st];
        __syncthreads();
    }
    if (tid == 0) atomicAdd(&g_acc[0], red[0]);
}

// ============================================================
__global__ void finalize_kernel(float* __restrict__ p_sc) {
    __shared__ float red[256];
    int tid = threadIdx.x;
    float s = 0.f;
    for (int i = tid; i < D_DIM; i += 256) {
        float cs = g_colsum[i];
        s += cs * cs;
    }
    red[tid] = s;
    __syncthreads();
    for (int st = 128; st > 0; st >>= 1) {
        if (tid < st) red[tid] += red[tid + st];
        __syncthreads();
    }
    if (tid == 0) {
        float TV  = g_acc[1] - red[0] / (float)B_N;
        float SSE = g_acc[0];
        p_sc[0] = SSE / TV;
        p_sc[1] = 0.f;
        p_sc[2] = 0.f;
        p_sc[3] = 0.f;
        p_sc[4] = SSE / (float)B_N;
    }
}

// ============================================================
extern "C" void kernel_launch(void* const* d_in, const int* in_sizes, int n_in,
                              void* d_out, int out_size)
{
    const float *x = nullptr, *We = nullptr, *be = nullptr, *Wd = nullptr, *bd = nullptr;
    int big_seen = 0;
    for (int i = 0; i < n_in; i++) {
        int sz = in_sizes[i];
        const float* p = (const float*)d_in[i];
        if (sz == (int)SZ_SAE)          x = p;
        else if (sz == N_LAT * D_DIM)   { if (big_seen++ == 0) We = p; else Wd = p; }
        else if (sz == N_LAT)           be = p;
        else if (sz == D_DIM)           bd = p;
    }

    float* out = (float*)d_out;
    float *p_sae = nullptr, *p_feat = nullptr, *p_ta = nullptr, *p_ti = nullptr, *p_sc = nullptr;

    if ((size_t)out_size == TOTAL_FULL) {
        p_sae  = out;
        p_feat = out + SZ_SAE;
        p_ta   = out + SZ_SAE + SZ_FEAT;
        p_ti   = p_ta + SZ_TA;
        p_sc   = p_ti + SZ_TA;
    } else if ((size_t)out_size == TOTAL_NOFEAT) {
        p_sae = out;
        p_ta  = out + SZ_SAE;
        p_ti  = p_ta + SZ_TA;
        p_sc  = p_ti + SZ_TA;
    } else {
        p_sae = out;
    }

    if (!p_feat) {
        void* fp = nullptr;
        cudaGetSymbolAddress(&fp, g_feat_fallback);
        p_feat = (float*)fp;
    }

    init_kernel<<<1, 32>>>();
    xc_kernel<<<(B_N * D_DIM / 4) / 256, 256>>>(x, bd);
    colstats_kernel<<<D_DIM / 256, 256>>>(x);
    encode_gemm<<<dim3(B_N / 128, N_LAT / 128), 256>>>(We, be, p_feat);
    cudaFuncSetAttribute(topk_kernel, cudaFuncAttributeMaxDynamicSharedMemorySize, TOPK_SMEM);
    topk_kernel<<<B_N, 256, TOPK_SMEM>>>(p_feat, p_ta, p_ti);
    decode_kernel<<<B_N, 256>>>(x, Wd, bd, p_sae);
    if (p_sc) finalize_kernel<<<1, 256>>>(p_sc);
}

// round 9
// speedup vs baseline: 1.2798x; 1.2406x over previous
#include <cuda_runtime.h>
#include <cstdint>

#define B_N   4096
#define D_DIM 1024
#define N_LAT 32768
#define TOPK  64

// frozen arithmetic: 2 k-panels of 512, fresh acc, fl(P0+P1), +b_enc, relu
#define NT 32                 // k-tiles of 32
#define TILES_PER_CHUNK 16    // 512/32

// ---- output layout (flattened tuple concat, f32) ----
#define SZ_SAE  ((size_t)B_N * D_DIM)
#define SZ_FEAT ((size_t)B_N * N_LAT)
#define SZ_TA   ((size_t)B_N * TOPK)
#define TOTAL_FULL (SZ_SAE + SZ_FEAT + SZ_TA + SZ_TA + 5)
#define TOTAL_NOFEAT (SZ_SAE + SZ_TA + SZ_TA + 5)

// ---- scratch ----
__device__ float g_top_val[B_N * TOPK];
__device__ int   g_top_idx[B_N * TOPK];
__device__ float g_colsum[D_DIM];
__device__ float g_acc[4];
__device__ float g_xc[(size_t)B_N * D_DIM];          // x - b_dec
__device__ float g_feat_fallback[(size_t)B_N * N_LAT];

#define FMA2(c,a,b) asm("fma.rn.f32x2 %0, %1, %2, %3;" : "=l"(c) : "l"(a), "l"(b), "l"(c))
#define ADD2(c,a,b) asm("add.rn.f32x2 %0, %1, %2;"     : "=l"(c) : "l"(a), "l"(b))

__device__ __forceinline__ float f2lo(unsigned long long v) { return __uint_as_float((unsigned)v); }
__device__ __forceinline__ float f2hi(unsigned long long v) { return __uint_as_float((unsigned)(v >> 32)); }
__device__ __forceinline__ unsigned long long fdup(float f) {
    unsigned u = __float_as_uint(f);
    return ((unsigned long long)u << 32) | u;
}

// ============================================================
__global__ void init_kernel() {
    int t = threadIdx.x;
    if (t < 4) g_acc[t] = 0.0f;
}

// xc = x - b_dec (elementwise, same fl as reference)
__global__ void xc_kernel(const float* __restrict__ X, const float* __restrict__ bdec) {
    int i = blockIdx.x * blockDim.x + threadIdx.x;      // float4 index
    float4 v = ((const float4*)X)[i];
    float4 d = ((const float4*)bdec)[i & 255];
    v.x -= d.x; v.y -= d.y; v.z -= d.z; v.w -= d.w;
    ((float4*)g_xc)[i] = v;
}

// ============================================================
__global__ void colstats_kernel(const float* __restrict__ X) {
    int c = blockIdx.x * blockDim.x + threadIdx.x;
    float s = 0.f, q = 0.f;
    #pragma unroll 4
    for (int n = 0; n < B_N; n++) {
        float v = X[(size_t)n * D_DIM + c];
        s += v;
        q += v * v;
    }
    g_colsum[c] = s;
    atomicAdd(&g_acc[1], q);
}

// ============================================================
// encode GEMM, FFMA2, 256 threads, 8m x 8n per thread.
// BK=32 (full 128B gmem rows per tile). B compute cols split tx*4 / 64+tx*4
// for conflict-free LDS.128. A in smem as dup (a,a) pairs. 96KB dyn smem.
// Per-element k-order preserved exactly (2 panels of 512, fl(P0+P1)).
// ============================================================
__global__ __launch_bounds__(256, 1)
void encode_gemm(const float* __restrict__ W,
                 const float* __restrict__ benc,
                 float* __restrict__ C)
{
    extern __shared__ char smem_raw[];
    unsigned long long* As2 = (unsigned long long*)smem_raw;      // [2][32][128] = 64KB
    float*              Bs  = (float*)(smem_raw + 65536);         // [2][32][128] = 32KB

    int tid = threadIdx.x;
    int tx  = tid & 15;          // n group
    int ty  = tid >> 4;          // m group
    int ty8 = ty * 8;
    int tx4 = tx * 4;
    int m0 = blockIdx.x * 128;
    int n0 = blockIdx.y * 128;

    int lr = tid >> 1;           // 0..127 loader row
    int lc = (tid & 1) << 4;     // 0 or 16 loader k-offset

    const float* aptr = g_xc + (size_t)(m0 + lr) * D_DIM + lc;
    const float* bptr = W    + (size_t)(n0 + lr) * D_DIM + lc;

    float4 ra[4], rb[4];

    // prologue: tile 0 -> stage 0
    #pragma unroll
    for (int q = 0; q < 4; q++) {
        ra[q] = *(const float4*)(aptr + q * 4);
        rb[q] = *(const float4*)(bptr + q * 4);
    }
    #pragma unroll
    for (int q = 0; q < 4; q++) {
        const float* rf = (const float*)&ra[q];
        const float* bf = (const float*)&rb[q];
        #pragma unroll
        for (int j = 0; j < 4; j++) {
            As2[(lc + q * 4 + j) * 128 + lr] = fdup(rf[j]);
            Bs [(lc + q * 4 + j) * 128 + lr] = bf[j];
        }
    }
    // prefetch tile 1
    #pragma unroll
    for (int q = 0; q < 4; q++) {
        ra[q] = *(const float4*)(aptr + 32 + q * 4);
        rb[q] = *(const float4*)(bptr + 32 + q * 4);
    }
    __syncthreads();

    unsigned long long acc[8][4], tot[8][4];
    #pragma unroll
    for (int i = 0; i < 8; i++)
        #pragma unroll
        for (int j = 0; j < 4; j++) acc[i][j] = 0ULL;

    for (int t = 0; t < NT; t++) {
        int s = t & 1;
        const unsigned long long* As_s = As2 + s * 4096;
        const float*              Bs_s = Bs  + s * 4096;
        #pragma unroll
        for (int kk = 0; kk < 32; kk++) {
            const ulonglong2* ap  = (const ulonglong2*)(As_s + kk * 128 + ty8);
            const ulonglong2* bp0 = (const ulonglong2*)(Bs_s + kk * 128 + tx4);
            const ulonglong2* bp1 = (const ulonglong2*)(Bs_s + kk * 128 + 64 + tx4);
            ulonglong2 bl = *bp0;                    // (b0,b1),(b2,b3) at tx4
            ulonglong2 bh = *bp1;                    // pairs at 64+tx4
            ulonglong2 a01 = ap[0], a23 = ap[1], a45 = ap[2], a67 = ap[3];
            #pragma unroll
            for (int i = 0; i < 8; i++) {
                unsigned long long av =
                    (i < 2) ? ((i & 1) ? a01.y : a01.x) :
                    (i < 4) ? ((i & 1) ? a23.y : a23.x) :
                    (i < 6) ? ((i & 1) ? a45.y : a45.x) :
                              ((i & 1) ? a67.y : a67.x);
                FMA2(acc[i][0], av, bl.x);
                FMA2(acc[i][1], av, bl.y);
                FMA2(acc[i][2], av, bh.x);
                FMA2(acc[i][3], av, bh.y);
            }
        }

        // chunk boundary: P0 done -> move to tot (exact), restart acc
        if (t == TILES_PER_CHUNK - 1) {
            #pragma unroll
            for (int i = 0; i < 8; i++)
                #pragma unroll
                for (int j = 0; j < 4; j++) {
                    tot[i][j] = acc[i][j];
                    acc[i][j] = 0ULL;
                }
        }

        if (t < NT - 1) {
            int sn = (t + 1) & 1;
            unsigned long long* As_n = As2 + sn * 4096;
            float*              Bs_n = Bs  + sn * 4096;
            #pragma unroll
            for (int q = 0; q < 4; q++) {
                const float* rf = (const float*)&ra[q];
                const float* bf = (const float*)&rb[q];
                #pragma unroll
                for (int j = 0; j < 4; j++) {
                    As_n[(lc + q * 4 + j) * 128 + lr] = fdup(rf[j]);
                    Bs_n[(lc + q * 4 + j) * 128 + lr] = bf[j];
                }
            }
            if (t < NT - 2) {
                #pragma unroll
                for (int q = 0; q < 4; q++) {
                    ra[q] = *(const float4*)(aptr + (t + 2) * 32 + q * 4);
                    rb[q] = *(const float4*)(bptr + (t + 2) * 32 + q * 4);
                }
            }
        }
        __syncthreads();
    }

    // tot = fl(P0 + P1), lanewise rn adds == scalar
    #pragma unroll
    for (int i = 0; i < 8; i++)
        #pragma unroll
        for (int j = 0; j < 4; j++)
            ADD2(tot[i][j], tot[i][j], acc[i][j]);

    float4 bev0 = *(const float4*)(benc + n0 + tx4);
    float4 bev1 = *(const float4*)(benc + n0 + 64 + tx4);
    #pragma unroll
    for (int i = 0; i < 8; i++) {
        size_t row = (size_t)(m0 + ty8 + i);
        float4 o0, o1;
        o0.x = fmaxf(f2lo(tot[i][0]) + bev0.x, 0.f);
        o0.y = fmaxf(f2hi(tot[i][0]) + bev0.y, 0.f);
        o0.z = fmaxf(f2lo(tot[i][1]) + bev0.z, 0.f);
        o0.w = fmaxf(f2hi(tot[i][1]) + bev0.w, 0.f);
        o1.x = fmaxf(f2lo(tot[i][2]) + bev1.x, 0.f);
        o1.y = fmaxf(f2hi(tot[i][2]) + bev1.y, 0.f);
        o1.z = fmaxf(f2lo(tot[i][3]) + bev1.z, 0.f);
        o1.w = fmaxf(f2hi(tot[i][3]) + bev1.w, 0.f);
        *(float4*)(C + row * N_LAT + n0 + tx4)      = o0;
        *(float4*)(C + row * N_LAT + n0 + 64 + tx4) = o1;
    }
}

// ============================================================
// top-k per row (unchanged, passing)
// ============================================================
#define CAP_B 4096
#define TOPK_SMEM ((32768 + 2048 + CAP_B) * 4)

__global__ void topk_kernel(const float* __restrict__ feat,
                            float* __restrict__ p_ta, float* __restrict__ p_ti)
{
    extern __shared__ uint32_t dyn[];
    uint32_t* sv   = dyn;
    uint32_t* hist = sv + 32768;
    int*      listB = (int*)(hist + 2048);

    __shared__ int   csum[256];
    __shared__ int   red[256];
    __shared__ float pv[64];
    __shared__ int   pi[64];
    __shared__ int   listA[64];
    __shared__ int   tiesel[64];
    __shared__ uint32_t s_prefix;
    __shared__ int   s_kr, s_cntA, s_cntB, s_last;

    int tid = threadIdx.x;
    int row = blockIdx.x;

    const float4* src = (const float4*)(feat + (size_t)row * N_LAT);
    uint4* dst = (uint4*)sv;
    for (int i = tid; i < N_LAT / 4; i += 256) {
        float4 v = src[i];
        uint4 u;
        u.x = __float_as_uint(v.x); u.y = __float_as_uint(v.y);
        u.z = __float_as_uint(v.z); u.w = __float_as_uint(v.w);
        dst[i] = u;
    }
    __syncthreads();

    uint32_t prefix = 0;
    int Kr = TOPK;
    const int SH[3] = {21, 10, 0};
    const int NB[3] = {11, 11, 10};

    for (int lvl = 0; lvl < 3; lvl++) {
        int sh = SH[lvl], nbits = NB[lvl];
        int nbins = 1 << nbits;
        uint32_t mask = (uint32_t)(nbins - 1);
        int hib = sh + nbits;
        for (int i = tid; i < nbins; i += 256) hist[i] = 0;
        __syncthreads();
        int zloc = 0;
        for (int i = tid; i < N_LAT; i += 256) {
            uint32_t u = sv[i];
            bool match = (lvl == 0) || ((u >> hib) == prefix);
            if (match) {
                if (u == 0u) zloc++;
                else atomicAdd(&hist[(u >> sh) & mask], 1u);
            }
        }
        if (zloc) atomicAdd(&hist[0], (uint32_t)zloc);
        __syncthreads();
        int nch = nbins >> 3;
        if (tid < nch) {
            int s = 0;
            #pragma unroll
            for (int j = 0; j < 8; j++) s += (int)hist[tid * 8 + j];
            csum[tid] = s;
        }
        __syncthreads();
        if (tid == 0) {
            int acc = 0, c = nch - 1;
            for (; c > 0; c--) {
                if (acc + csum[c] >= Kr) break;
                acc += csum[c];
            }
            int b = c * 8 + 7;
            for (; b > c * 8; b--) {
                int h = (int)hist[b];
                if (acc + h >= Kr) break;
                acc += h;
            }
            s_prefix = (prefix << nbits) | (uint32_t)b;
            s_kr = Kr - acc;
        }
        __syncthreads();
        prefix = s_prefix;
        Kr = s_kr;
        __syncthreads();
    }

    uint32_t T = prefix;
    int Need = Kr;
    if (tid == 0) { s_cntA = 0; s_cntB = 0; }
    __syncthreads();
    for (int i = tid; i < N_LAT; i += 256) {
        uint32_t u = sv[i];
        if (u > T) {
            int p = atomicAdd(&s_cntA, 1);
            if (p < 64) listA[p] = i;
        } else if (u == T) {
            int p = atomicAdd(&s_cntB, 1);
            if (p < CAP_B) listB[p] = i;
        }
    }
    __syncthreads();
    int cA = s_cntA, cB = s_cntB;

    int last = -1;
    for (int s = 0; s < Need; s++) {
        int loc = 0x7FFFFFFF;
        if (cB <= CAP_B) {
            for (int i = tid; i < cB; i += 256) {
                int ix = listB[i];
                if (ix > last && ix < loc) loc = ix;
            }
        } else {
            for (int i = tid; i < N_LAT; i += 256) {
                if (sv[i] == T && i > last && i < loc) loc = i;
            }
        }
        red[tid] = loc;
        __syncthreads();
        for (int st = 128; st > 0; st >>= 1) {
            if (tid < st) red[tid] = min(red[tid], red[tid + st]);
            __syncthreads();
        }
        if (tid == 0) { tiesel[s] = red[0]; s_last = red[0]; }
        __syncthreads();
        last = s_last;
    }

    if (tid < 64) {
        float v; int ix;
        if (tid < cA) { ix = listA[tid]; v = __uint_as_float(sv[ix]); }
        else          { ix = tiesel[tid - cA]; v = __uint_as_float(T); }
        pv[tid] = v; pi[tid] = ix;
    }
    __syncthreads();
    if (tid < 64) {
        float v = pv[tid]; int ix = pi[tid];
        int rank = 0;
        #pragma unroll 8
        for (int j = 0; j < 64; j++) {
            float vj = pv[j]; int ij = pi[j];
            if (vj > v || (vj == v && ij < ix)) rank++;
        }
        size_t o = (size_t)row * TOPK + rank;
        g_top_val[o] = v;
        g_top_idx[o] = ix;
        if (p_ta) p_ta[o] = v;
        if (p_ti) p_ti[o] = (float)ix;
    }
}

// ============================================================
__global__ void decode_kernel(const float* __restrict__ X,
                              const float* __restrict__ Wd,
                              const float* __restrict__ bdec,
                              float* __restrict__ sae)
{
    __shared__ float sval[64];
    __shared__ int   sidx[64];
    __shared__ float red[256];
    int tid = threadIdx.x, row = blockIdx.x;
    if (tid < 64) {
        sval[tid] = g_top_val[row * TOPK + tid];
        sidx[tid] = g_top_idx[row * TOPK + tid];
    }
    __syncthreads();
    int d0 = tid * 4;
    float4 acc = *(const float4*)(bdec + d0);
    #pragma unroll 4
    for (int k = 0; k < TOPK; k++) {
        float a = sval[k];
        float4 w = *(const float4*)(Wd + (size_t)sidx[k] * D_DIM + d0);
        acc.x += a * w.x; acc.y += a * w.y; acc.z += a * w.z; acc.w += a * w.w;
    }
    size_t o = (size_t)row * D_DIM + d0;
    if (sae) *(float4*)(sae + o) = acc;
    float4 xv = *(const float4*)(X + o);
    float ex = acc.x - xv.x, ey = acc.y - xv.y, ez = acc.z - xv.z, ew = acc.w - xv.w;
    red[tid] = ex * ex + ey * ey + ez * ez + ew * ew;
    __syncthreads();
    for (int st = 128; st > 0; st >>= 1) {
        if (tid < st) red[tid] += red[tid + st];
        __syncthreads();
    }
    if (tid == 0) atomicAdd(&g_acc[0], red[0]);
}

// ============================================================
__global__ void finalize_kernel(float* __restrict__ p_sc) {
    __shared__ float red[256];
    int tid = threadIdx.x;
    float s = 0.f;
    for (int i = tid; i < D_DIM; i += 256) {
        float cs = g_colsum[i];
        s += cs * cs;
    }
    red[tid] = s;
    __syncthreads();
    for (int st = 128; st > 0; st >>= 1) {
        if (tid < st) red[tid] += red[tid + st];
        __syncthreads();
    }
    if (tid == 0) {
        float TV  = g_acc[1] - red[0] / (float)B_N;
        float SSE = g_acc[0];
        p_sc[0] = SSE / TV;
        p_sc[1] = 0.f;
        p_sc[2] = 0.f;
        p_sc[3] = 0.f;
        p_sc[4] = SSE / (float)B_N;
    }
}

// ============================================================
extern "C" void kernel_launch(void* const* d_in, const int* in_sizes, int n_in,
                              void* d_out, int out_size)
{
    const float *x = nullptr, *We = nullptr, *be = nullptr, *Wd = nullptr, *bd = nullptr;
    int big_seen = 0;
    for (int i = 0; i < n_in; i++) {
        int sz = in_sizes[i];
        const float* p = (const float*)d_in[i];
        if (sz == (int)SZ_SAE)          x = p;
        else if (sz == N_LAT * D_DIM)   { if (big_seen++ == 0) We = p; else Wd = p; }
        else if (sz == N_LAT)           be = p;
        else if (sz == D_DIM)           bd = p;
    }

    float* out = (float*)d_out;
    float *p_sae = nullptr, *p_feat = nullptr, *p_ta = nullptr, *p_ti = nullptr, *p_sc = nullptr;

    if ((size_t)out_size == TOTAL_FULL) {
        p_sae  = out;
        p_feat = out + SZ_SAE;
        p_ta   = out + SZ_SAE + SZ_FEAT;
        p_ti   = p_ta + SZ_TA;
        p_sc   = p_ti + SZ_TA;
    } else if ((size_t)out_size == TOTAL_NOFEAT) {
        p_sae = out;
        p_ta  = out + SZ_SAE;
        p_ti  = p_ta + SZ_TA;
        p_sc  = p_ti + SZ_TA;
    } else {
        p_sae = out;
    }

    if (!p_feat) {
        void* fp = nullptr;
        cudaGetSymbolAddress(&fp, g_feat_fallback);
        p_feat = (float*)fp;
    }

    init_kernel<<<1, 32>>>();
    xc_kernel<<<(B_N * D_DIM / 4) / 256, 256>>>(x, bd);
    colstats_kernel<<<D_DIM / 256, 256>>>(x);
    cudaFuncSetAttribute(encode_gemm, cudaFuncAttributeMaxDynamicSharedMemorySize, 98304);
    encode_gemm<<<dim3(B_N / 128, N_LAT / 128), 256, 98304>>>(We, be, p_feat);
    cudaFuncSetAttribute(topk_kernel, cudaFuncAttributeMaxDynamicSharedMemorySize, TOPK_SMEM);
    topk_kernel<<<B_N, 256, TOPK_SMEM>>>(p_feat, p_ta, p_ti);
    decode_kernel<<<B_N, 256>>>(x, Wd, bd, p_sae);
    if (p_sc) finalize_kernel<<<1, 256>>>(p_sc);
}

// round 10
// speedup vs baseline: 1.2823x; 1.0020x over previous
#include <cuda_runtime.h>
#include <cstdint>

#define B_N   4096
#define D_DIM 1024
#define N_LAT 32768
#define TOPK  64

// frozen arithmetic: 2 k-panels of 512, fresh acc, fl(P0+P1), +b_enc, relu
#define NT 32                 // k-tiles of 32
#define TILES_PER_CHUNK 16    // 512/32

// ---- output layout (flattened tuple concat, f32) ----
#define SZ_SAE  ((size_t)B_N * D_DIM)
#define SZ_FEAT ((size_t)B_N * N_LAT)
#define SZ_TA   ((size_t)B_N * TOPK)
#define TOTAL_FULL (SZ_SAE + SZ_FEAT + SZ_TA + SZ_TA + 5)
#define TOTAL_NOFEAT (SZ_SAE + SZ_TA + SZ_TA + 5)

// ---- scratch ----
__device__ float g_top_val[B_N * TOPK];
__device__ int   g_top_idx[B_N * TOPK];
__device__ float g_colsum[D_DIM];
__device__ float g_acc[4];
__device__ float g_xc[(size_t)B_N * D_DIM];          // x - b_dec
__device__ float g_feat_fallback[(size_t)B_N * N_LAT];

#define FMA2(c,a,b) asm("fma.rn.f32x2 %0, %1, %2, %3;" : "=l"(c) : "l"(a), "l"(b), "l"(c))
#define ADD2(c,a,b) asm("add.rn.f32x2 %0, %1, %2;"     : "=l"(c) : "l"(a), "l"(b))

__device__ __forceinline__ float f2lo(unsigned long long v) { return __uint_as_float((unsigned)v); }
__device__ __forceinline__ float f2hi(unsigned long long v) { return __uint_as_float((unsigned)(v >> 32)); }
__device__ __forceinline__ unsigned long long fdup(float f) {
    unsigned u = __float_as_uint(f);
    return ((unsigned long long)u << 32) | u;
}

// ============================================================
__global__ void init_kernel() {
    int t = threadIdx.x;
    if (t < 4) g_acc[t] = 0.0f;
}

// xc = x - b_dec (elementwise, same fl as reference)
__global__ void xc_kernel(const float* __restrict__ X, const float* __restrict__ bdec) {
    int i = blockIdx.x * blockDim.x + threadIdx.x;      // float4 index
    float4 v = ((const float4*)X)[i];
    float4 d = ((const float4*)bdec)[i & 255];
    v.x -= d.x; v.y -= d.y; v.z -= d.z; v.w -= d.w;
    ((float4*)g_xc)[i] = v;
}

// ============================================================
__global__ void colstats_kernel(const float* __restrict__ X) {
    int c = blockIdx.x * blockDim.x + threadIdx.x;
    float s = 0.f, q = 0.f;
    #pragma unroll 4
    for (int n = 0; n < B_N; n++) {
        float v = X[(size_t)n * D_DIM + c];
        s += v;
        q += v * v;
    }
    g_colsum[c] = s;
    atomicAdd(&g_acc[1], q);
}

// ============================================================
// encode GEMM, FFMA2, 256 threads, 8m x 8n per thread.
// Warp map: lane -> (tx = lane&7, ty = lane>>3); warp w -> (wm = w>>1, wn = w&1).
// Thread rows: wm*32 + i*8 + ty*2 + {0,1}; cols: wn*64 + tx*4 + {0..3} and +32.
// Every LDS.128 touches <= 128B -> conflict-free 1 wavefront.
// BK=32, 96KB dyn smem, 2-stage. Per-element k-order preserved exactly.
// ============================================================
__global__ __launch_bounds__(256, 1)
void encode_gemm(const float* __restrict__ W,
                 const float* __restrict__ benc,
                 float* __restrict__ C)
{
    extern __shared__ char smem_raw[];
    unsigned long long* As2 = (unsigned long long*)smem_raw;      // [2][32][128] = 64KB dup pairs
    float*              Bs  = (float*)(smem_raw + 65536);         // [2][32][128] = 32KB

    int tid  = threadIdx.x;
    int lane = tid & 31;
    int w    = tid >> 5;
    int tx   = lane & 7;
    int ty   = lane >> 3;        // 0..3
    int wm   = w >> 1;           // 0..3
    int wn   = w & 1;            // 0..1
    int mbase = wm * 32 + ty * 2;
    int nbase = wn * 64 + tx * 4;
    int m0 = blockIdx.x * 128;
    int n0 = blockIdx.y * 128;

    int lr = tid >> 1;           // 0..127 loader row
    int lc = (tid & 1) << 4;     // 0 or 16 loader k-offset

    const float* aptr = g_xc + (size_t)(m0 + lr) * D_DIM + lc;
    const float* bptr = W    + (size_t)(n0 + lr) * D_DIM + lc;

    float4 ra[4], rb[4];

    // prologue: tile 0 -> stage 0
    #pragma unroll
    for (int q = 0; q < 4; q++) {
        ra[q] = *(const float4*)(aptr + q * 4);
        rb[q] = *(const float4*)(bptr + q * 4);
    }
    #pragma unroll
    for (int q = 0; q < 4; q++) {
        const float* rf = (const float*)&ra[q];
        const float* bf = (const float*)&rb[q];
        #pragma unroll
        for (int j = 0; j < 4; j++) {
            As2[(lc + q * 4 + j) * 128 + lr] = fdup(rf[j]);
            Bs [(lc + q * 4 + j) * 128 + lr] = bf[j];
        }
    }
    // prefetch tile 1
    #pragma unroll
    for (int q = 0; q < 4; q++) {
        ra[q] = *(const float4*)(aptr + 32 + q * 4);
        rb[q] = *(const float4*)(bptr + 32 + q * 4);
    }
    __syncthreads();

    // acc[r][j]: r = i*2+e -> global row m0 + mbase + i*8 + e ; j -> n pair
    unsigned long long acc[8][4], tot[8][4];
    #pragma unroll
    for (int i = 0; i < 8; i++)
        #pragma unroll
        for (int j = 0; j < 4; j++) acc[i][j] = 0ULL;

    for (int t = 0; t < NT; t++) {
        int s = t & 1;
        const unsigned long long* As_s = As2 + s * 4096;
        const float*              Bs_s = Bs  + s * 4096;
        #pragma unroll
        for (int kk = 0; kk < 32; kk++) {
            ulonglong2 bl = *(const ulonglong2*)(Bs_s + kk * 128 + nbase);
            ulonglong2 bh = *(const ulonglong2*)(Bs_s + kk * 128 + 32 + nbase);
            #pragma unroll
            for (int i = 0; i < 4; i++) {
                ulonglong2 av = *(const ulonglong2*)(As_s + kk * 128 + mbase + i * 8);
                FMA2(acc[i * 2 + 0][0], av.x, bl.x);
                FMA2(acc[i * 2 + 0][1], av.x, bl.y);
                FMA2(acc[i * 2 + 0][2], av.x, bh.x);
                FMA2(acc[i * 2 + 0][3], av.x, bh.y);
                FMA2(acc[i * 2 + 1][0], av.y, bl.x);
                FMA2(acc[i * 2 + 1][1], av.y, bl.y);
                FMA2(acc[i * 2 + 1][2], av.y, bh.x);
                FMA2(acc[i * 2 + 1][3], av.y, bh.y);
            }
        }

        // chunk boundary: P0 done -> move to tot (exact), restart acc
        if (t == TILES_PER_CHUNK - 1) {
            #pragma unroll
            for (int i = 0; i < 8; i++)
                #pragma unroll
                for (int j = 0; j < 4; j++) {
                    tot[i][j] = acc[i][j];
                    acc[i][j] = 0ULL;
                }
        }

        if (t < NT - 1) {
            int sn = (t + 1) & 1;
            unsigned long long* As_n = As2 + sn * 4096;
            float*              Bs_n = Bs  + sn * 4096;
            #pragma unroll
            for (int q = 0; q < 4; q++) {
                const float* rf = (const float*)&ra[q];
                const float* bf = (const float*)&rb[q];
                #pragma unroll
                for (int j = 0; j < 4; j++) {
                    As_n[(lc + q * 4 + j) * 128 + lr] = fdup(rf[j]);
                    Bs_n[(lc + q * 4 + j) * 128 + lr] = bf[j];
                }
            }
            if (t < NT - 2) {
                #pragma unroll
                for (int q = 0; q < 4; q++) {
                    ra[q] = *(const float4*)(aptr + (t + 2) * 32 + q * 4);
                    rb[q] = *(const float4*)(bptr + (t + 2) * 32 + q * 4);
                }
            }
        }
        __syncthreads();
    }

    // tot = fl(P0 + P1), lanewise rn adds == scalar
    #pragma unroll
    for (int i = 0; i < 8; i++)
        #pragma unroll
        for (int j = 0; j < 4; j++)
            ADD2(tot[i][j], tot[i][j], acc[i][j]);

    float4 bev0 = *(const float4*)(benc + n0 + nbase);
    float4 bev1 = *(const float4*)(benc + n0 + 32 + nbase);
    #pragma unroll
    for (int r = 0; r < 8; r++) {
        int i = r >> 1, e = r & 1;
        size_t row = (size_t)(m0 + mbase + i * 8 + e);
        float4 o0, o1;
        o0.x = fmaxf(f2lo(tot[r][0]) + bev0.x, 0.f);
        o0.y = fmaxf(f2hi(tot[r][0]) + bev0.y, 0.f);
        o0.z = fmaxf(f2lo(tot[r][1]) + bev0.z, 0.f);
        o0.w = fmaxf(f2hi(tot[r][1]) + bev0.w, 0.f);
        o1.x = fmaxf(f2lo(tot[r][2]) + bev1.x, 0.f);
        o1.y = fmaxf(f2hi(tot[r][2]) + bev1.y, 0.f);
        o1.z = fmaxf(f2lo(tot[r][3]) + bev1.z, 0.f);
        o1.w = fmaxf(f2hi(tot[r][3]) + bev1.w, 0.f);
        *(float4*)(C + row * N_LAT + n0 + nbase)      = o0;
        *(float4*)(C + row * N_LAT + n0 + 32 + nbase) = o1;
    }
}

// ============================================================
// top-k per row (unchanged, passing)
// ============================================================
#define CAP_B 4096
#define TOPK_SMEM ((32768 + 2048 + CAP_B) * 4)

__global__ void topk_kernel(const float* __restrict__ feat,
                            float* __restrict__ p_ta, float* __restrict__ p_ti)
{
    extern __shared__ uint32_t dyn[];
    uint32_t* sv   = dyn;
    uint32_t* hist = sv + 32768;
    int*      listB = (int*)(hist + 2048);

    __shared__ int   csum[256];
    __shared__ int   red[256];
    __shared__ float pv[64];
    __shared__ int   pi[64];
    __shared__ int   listA[64];
    __shared__ int   tiesel[64];
    __shared__ uint32_t s_prefix;
    __shared__ int   s_kr, s_cntA, s_cntB, s_last;

    int tid = threadIdx.x;
    int row = blockIdx.x;

    const float4* src = (const float4*)(feat + (size_t)row * N_LAT);
    uint4* dst = (uint4*)sv;
    for (int i = tid; i < N_LAT / 4; i += 256) {
        float4 v = src[i];
        uint4 u;
        u.x = __float_as_uint(v.x); u.y = __float_as_uint(v.y);
        u.z = __float_as_uint(v.z); u.w = __float_as_uint(v.w);
        dst[i] = u;
    }
    __syncthreads();

    uint32_t prefix = 0;
    int Kr = TOPK;
    const int SH[3] = {21, 10, 0};
    const int NB[3] = {11, 11, 10};

    for (int lvl = 0; lvl < 3; lvl++) {
        int sh = SH[lvl], nbits = NB[lvl];
        int nbins = 1 << nbits;
        uint32_t mask = (uint32_t)(nbins - 1);
        int hib = sh + nbits;
        for (int i = tid; i < nbins; i += 256) hist[i] = 0;
        __syncthreads();
        int zloc = 0;
        for (int i = tid; i < N_LAT; i += 256) {
            uint32_t u = sv[i];
            bool match = (lvl == 0) || ((u >> hib) == prefix);
            if (match) {
                if (u == 0u) zloc++;
                else atomicAdd(&hist[(u >> sh) & mask], 1u);
            }
        }
        if (zloc) atomicAdd(&hist[0], (uint32_t)zloc);
        __syncthreads();
        int nch = nbins >> 3;
        if (tid < nch) {
            int s = 0;
            #pragma unroll
            for (int j = 0; j < 8; j++) s += (int)hist[tid * 8 + j];
            csum[tid] = s;
        }
        __syncthreads();
        if (tid == 0) {
            int acc = 0, c = nch - 1;
            for (; c > 0; c--) {
                if (acc + csum[c] >= Kr) break;
                acc += csum[c];
            }
            int b = c * 8 + 7;
            for (; b > c * 8; b--) {
                int h = (int)hist[b];
                if (acc + h >= Kr) break;
                acc += h;
            }
            s_prefix = (prefix << nbits) | (uint32_t)b;
            s_kr = Kr - acc;
        }
        __syncthreads();
        prefix = s_prefix;
        Kr = s_kr;
        __syncthreads();
    }

    uint32_t T = prefix;
    int Need = Kr;
    if (tid == 0) { s_cntA = 0; s_cntB = 0; }
    __syncthreads();
    for (int i = tid; i < N_LAT; i += 256) {
        uint32_t u = sv[i];
        if (u > T) {
            int p = atomicAdd(&s_cntA, 1);
            if (p < 64) listA[p] = i;
        } else if (u == T) {
            int p = atomicAdd(&s_cntB, 1);
            if (p < CAP_B) listB[p] = i;
        }
    }
    __syncthreads();
    int cA = s_cntA, cB = s_cntB;

    int last = -1;
    for (int s = 0; s < Need; s++) {
        int loc = 0x7FFFFFFF;
        if (cB <= CAP_B) {
            for (int i = tid; i < cB; i += 256) {
                int ix = listB[i];
                if (ix > last && ix < loc) loc = ix;
            }
        } else {
            for (int i = tid; i < N_LAT; i += 256) {
                if (sv[i] == T && i > last && i < loc) loc = i;
            }
        }
        red[tid] = loc;
        __syncthreads();
        for (int st = 128; st > 0; st >>= 1) {
            if (tid < st) red[tid] = min(red[tid], red[tid + st]);
            __syncthreads();
        }
        if (tid == 0) { tiesel[s] = red[0]; s_last = red[0]; }
        __syncthreads();
        last = s_last;
    }

    if (tid < 64) {
        float v; int ix;
        if (tid < cA) { ix = listA[tid]; v = __uint_as_float(sv[ix]); }
        else          { ix = tiesel[tid - cA]; v = __uint_as_float(T); }
        pv[tid] = v; pi[tid] = ix;
    }
    __syncthreads();
    if (tid < 64) {
        float v = pv[tid]; int ix = pi[tid];
        int rank = 0;
        #pragma unroll 8
        for (int j = 0; j < 64; j++) {
            float vj = pv[j]; int ij = pi[j];
            if (vj > v || (vj == v && ij < ix)) rank++;
        }
        size_t o = (size_t)row * TOPK + rank;
        g_top_val[o] = v;
        g_top_idx[o] = ix;
        if (p_ta) p_ta[o] = v;
        if (p_ti) p_ti[o] = (float)ix;
    }
}

// ============================================================
__global__ void decode_kernel(const float* __restrict__ X,
                              const float* __restrict__ Wd,
                              const float* __restrict__ bdec,
                              float* __restrict__ sae)
{
    __shared__ float sval[64];
    __shared__ int   sidx[64];
    __shared__ float red[256];
    int tid = threadIdx.x, row = blockIdx.x;
    if (tid < 64) {
        sval[tid] = g_top_val[row * TOPK + tid];
        sidx[tid] = g_top_idx[row * TOPK + tid];
    }
    __syncthreads();
    int d0 = tid * 4;
    float4 acc = *(const float4*)(bdec + d0);
    #pragma unroll 4
    for (int k = 0; k < TOPK; k++) {
        float a = sval[k];
        float4 w = *(const float4*)(Wd + (size_t)sidx[k] * D_DIM + d0);
        acc.x += a * w.x; acc.y += a * w.y; acc.z += a * w.z; acc.w += a * w.w;
    }
    size_t o = (size_t)row * D_DIM + d0;
    if (sae) *(float4*)(sae + o) = acc;
    float4 xv = *(const float4*)(X + o);
    float ex = acc.x - xv.x, ey = acc.y - xv.y, ez = acc.z - xv.z, ew = acc.w - xv.w;
    red[tid] = ex * ex + ey * ey + ez * ez + ew * ew;
    __syncthreads();
    for (int st = 128; st > 0; st >>= 1) {
        if (tid < st) red[tid] += red[tid + st];
        __syncthreads();
    }
    if (tid == 0) atomicAdd(&g_acc[0], red[0]);
}

// ============================================================
__global__ void finalize_kernel(float* __restrict__ p_sc) {
    __shared__ float red[256];
    int tid = threadIdx.x;
    float s = 0.f;
    for (int i = tid; i < D_DIM; i += 256) {
        float cs = g_colsum[i];
        s += cs * cs;
    }
    red[tid] = s;
    __syncthreads();
    for (int st = 128; st > 0; st >>= 1) {
        if (tid < st) red[tid] += red[tid + st];
        __syncthreads();
    }
    if (tid == 0) {
        float TV  = g_acc[1] - red[0] / (float)B_N;
        float SSE = g_acc[0];
        p_sc[0] = SSE / TV;
        p_sc[1] = 0.f;
        p_sc[2] = 0.f;
        p_sc[3] = 0.f;
        p_sc[4] = SSE / (float)B_N;
    }
}

// ============================================================
extern "C" void kernel_launch(void* const* d_in, const int* in_sizes, int n_in,
                              void* d_out, int out_size)
{
    const float *x = nullptr, *We = nullptr, *be = nullptr, *Wd = nullptr, *bd = nullptr;
    int big_seen = 0;
    for (int i = 0; i < n_in; i++) {
        int sz = in_sizes[i];
        const float* p = (const float*)d_in[i];
        if (sz == (int)SZ_SAE)          x = p;
        else if (sz == N_LAT * D_DIM)   { if (big_seen++ == 0) We = p; else Wd = p; }
        else if (sz == N_LAT)           be = p;
        else if (sz == D_DIM)           bd = p;
    }

    float* out = (float*)d_out;
    float *p_sae = nullptr, *p_feat = nullptr, *p_ta = nullptr, *p_ti = nullptr, *p_sc = nullptr;

    if ((size_t)out_size == TOTAL_FULL) {
        p_sae  = out;
        p_feat = out + SZ_SAE;
        p_ta   = out + SZ_SAE + SZ_FEAT;
        p_ti   = p_ta + SZ_TA;
        p_sc   = p_ti + SZ_TA;
    } else if ((size_t)out_size == TOTAL_NOFEAT) {
        p_sae = out;
        p_ta  = out + SZ_SAE;
        p_ti  = p_ta + SZ_TA;
        p_sc  = p_ti + SZ_TA;
    } else {
        p_sae = out;
    }

    if (!p_feat) {
        void* fp = nullptr;
        cudaGetSymbolAddress(&fp, g_feat_fallback);
        p_feat = (float*)fp;
    }

    init_kernel<<<1, 32>>>();
    xc_kernel<<<(B_N * D_DIM / 4) / 256, 256>>>(x, bd);
    colstats_kernel<<<D_DIM / 256, 256>>>(x);
    cudaFuncSetAttribute(encode_gemm, cudaFuncAttributeMaxDynamicSharedMemorySize, 98304);
    encode_gemm<<<dim3(B_N / 128, N_LAT / 128), 256, 98304>>>(We, be, p_feat);
    cudaFuncSetAttribute(topk_kernel, cudaFuncAttributeMaxDynamicSharedMemorySize, TOPK_SMEM);
    topk_kernel<<<B_N, 256, TOPK_SMEM>>>(p_feat, p_ta, p_ti);
    decode_kernel<<<B_N, 256>>>(x, Wd, bd, p_sae);
    if (p_sc) finalize_kernel<<<1, 256>>>(p_sc);
}

// round 11
// speedup vs baseline: 1.4527x; 1.1329x over previous
#include <cuda_runtime.h>
#include <cstdint>

#define B_N   4096
#define D_DIM 1024
#define N_LAT 32768
#define TOPK  64

// frozen arithmetic: 2 k-panels of 512, fresh acc, fl(P0+P1), +b_enc, relu
#define NT 32                 // k-tiles of 32
#define TILES_PER_CHUNK 16    // 512/32

// ---- output layout (flattened tuple concat, f32) ----
#define SZ_SAE  ((size_t)B_N * D_DIM)
#define SZ_FEAT ((size_t)B_N * N_LAT)
#define SZ_TA   ((size_t)B_N * TOPK)
#define TOTAL_FULL (SZ_SAE + SZ_FEAT + SZ_TA + SZ_TA + 5)
#define TOTAL_NOFEAT (SZ_SAE + SZ_TA + SZ_TA + 5)

// ---- scratch ----
__device__ float g_top_val[B_N * TOPK];
__device__ int   g_top_idx[B_N * TOPK];
__device__ float g_colsum[D_DIM];
__device__ float g_acc[4];
__device__ float g_xc[(size_t)B_N * D_DIM];          // x - b_dec
__device__ float g_feat_fallback[(size_t)B_N * N_LAT];

#define FMA2(c,a,b) asm("fma.rn.f32x2 %0, %1, %2, %3;" : "=l"(c) : "l"(a), "l"(b), "l"(c))
#define ADD2(c,a,b) asm("add.rn.f32x2 %0, %1, %2;"     : "=l"(c) : "l"(a), "l"(b))
// register dup: (f,f) 64-bit pair, 1 ALU instr (alu pipe is idle; L1 is the bottleneck)
#define PAIR(d,f)   asm("mov.b64 %0, {%1, %1};"        : "=l"(d) : "r"(__float_as_uint(f)))

__device__ __forceinline__ float f2lo(unsigned long long v) { return __uint_as_float((unsigned)v); }
__device__ __forceinline__ float f2hi(unsigned long long v) { return __uint_as_float((unsigned)(v >> 32)); }

// ============================================================
__global__ void init_kernel() {
    int t = threadIdx.x;
    if (t < 4) g_acc[t] = 0.0f;
}

// xc = x - b_dec (elementwise, same fl as reference)
__global__ void xc_kernel(const float* __restrict__ X, const float* __restrict__ bdec) {
    int i = blockIdx.x * blockDim.x + threadIdx.x;      // float4 index
    float4 v = ((const float4*)X)[i];
    float4 d = ((const float4*)bdec)[i & 255];
    v.x -= d.x; v.y -= d.y; v.z -= d.z; v.w -= d.w;
    ((float4*)g_xc)[i] = v;
}

// ============================================================
__global__ void colstats_kernel(const float* __restrict__ X) {
    int c = blockIdx.x * blockDim.x + threadIdx.x;
    float s = 0.f, q = 0.f;
    #pragma unroll 4
    for (int n = 0; n < B_N; n++) {
        float v = X[(size_t)n * D_DIM + c];
        s += v;
        q += v * v;
    }
    g_colsum[c] = s;
    atomicAdd(&g_acc[1], q);
}

// ============================================================
// encode GEMM, FFMA2, 256 threads, 8m x 8n per thread.
// A in smem as PLAIN floats [k][128] (no dup) -> half the A LDS/STS bytes;
// (a,a) operand pairs built in registers via mov.b64 {f,f} (ALU, free).
// Rows ty*8..+7 contiguous (2x LDS.128); cols tx*4 and 64+tx*4 (conflict-split).
// BK=32, 64KB dyn smem, 2-stage. Per-element k-order preserved exactly.
// ============================================================
__global__ __launch_bounds__(256, 1)
void encode_gemm(const float* __restrict__ W,
                 const float* __restrict__ benc,
                 float* __restrict__ C)
{
    extern __shared__ char smem_raw[];
    float* As = (float*)smem_raw;                 // [2][32][128] = 32KB
    float* Bs = (float*)(smem_raw + 32768);       // [2][32][128] = 32KB

    int tid = threadIdx.x;
    int tx  = tid & 15;          // n group
    int ty  = tid >> 4;          // m group: rows ty*8..ty*8+7
    int ty8 = ty * 8;
    int tx4 = tx * 4;
    int m0 = blockIdx.x * 128;
    int n0 = blockIdx.y * 128;

    int lr = tid >> 1;           // 0..127 loader row
    int lc = (tid & 1) << 4;     // 0 or 16 loader k-offset

    const float* aptr = g_xc + (size_t)(m0 + lr) * D_DIM + lc;
    const float* bptr = W    + (size_t)(n0 + lr) * D_DIM + lc;

    float4 ra[4], rb[4];

    // prologue: tile 0 -> stage 0
    #pragma unroll
    for (int q = 0; q < 4; q++) {
        ra[q] = *(const float4*)(aptr + q * 4);
        rb[q] = *(const float4*)(bptr + q * 4);
    }
    #pragma unroll
    for (int q = 0; q < 4; q++) {
        const float* rf = (const float*)&ra[q];
        const float* bf = (const float*)&rb[q];
        #pragma unroll
        for (int j = 0; j < 4; j++) {
            As[(lc + q * 4 + j) * 128 + lr] = rf[j];
            Bs[(lc + q * 4 + j) * 128 + lr] = bf[j];
        }
    }
    // prefetch tile 1
    #pragma unroll
    for (int q = 0; q < 4; q++) {
        ra[q] = *(const float4*)(aptr + 32 + q * 4);
        rb[q] = *(const float4*)(bptr + 32 + q * 4);
    }
    __syncthreads();

    unsigned long long acc[8][4], tot[8][4];
    #pragma unroll
    for (int i = 0; i < 8; i++)
        #pragma unroll
        for (int j = 0; j < 4; j++) acc[i][j] = 0ULL;

    for (int t = 0; t < NT; t++) {
        int s = t & 1;
        const float* As_s = As + s * 4096;
        const float* Bs_s = Bs + s * 4096;
        #pragma unroll
        for (int kk = 0; kk < 32; kk++) {
            float4 a03 = *(const float4*)(As_s + kk * 128 + ty8);
            float4 a47 = *(const float4*)(As_s + kk * 128 + ty8 + 4);
            ulonglong2 bl = *(const ulonglong2*)(Bs_s + kk * 128 + tx4);
            ulonglong2 bh = *(const ulonglong2*)(Bs_s + kk * 128 + 64 + tx4);
            const float* af = (const float*)&a03;   // a03,a47 contiguous? keep explicit:
            float av[8];
            av[0] = a03.x; av[1] = a03.y; av[2] = a03.z; av[3] = a03.w;
            av[4] = a47.x; av[5] = a47.y; av[6] = a47.z; av[7] = a47.w;
            (void)af;
            #pragma unroll
            for (int i = 0; i < 8; i++) {
                unsigned long long a2;
                PAIR(a2, av[i]);
                FMA2(acc[i][0], a2, bl.x);
                FMA2(acc[i][1], a2, bl.y);
                FMA2(acc[i][2], a2, bh.x);
                FMA2(acc[i][3], a2, bh.y);
            }
        }

        // chunk boundary: P0 done -> move to tot (exact), restart acc
        if (t == TILES_PER_CHUNK - 1) {
            #pragma unroll
            for (int i = 0; i < 8; i++)
                #pragma unroll
                for (int j = 0; j < 4; j++) {
                    tot[i][j] = acc[i][j];
                    acc[i][j] = 0ULL;
                }
        }

        if (t < NT - 1) {
            int sn = (t + 1) & 1;
            float* As_n = As + sn * 4096;
            float* Bs_n = Bs + sn * 4096;
            #pragma unroll
            for (int q = 0; q < 4; q++) {
                const float* rf = (const float*)&ra[q];
                const float* bf = (const float*)&rb[q];
                #pragma unroll
                for (int j = 0; j < 4; j++) {
                    As_n[(lc + q * 4 + j) * 128 + lr] = rf[j];
                    Bs_n[(lc + q * 4 + j) * 128 + lr] = bf[j];
                }
            }
            if (t < NT - 2) {
                #pragma unroll
                for (int q = 0; q < 4; q++) {
                    ra[q] = *(const float4*)(aptr + (t + 2) * 32 + q * 4);
                    rb[q] = *(const float4*)(bptr + (t + 2) * 32 + q * 4);
                }
            }
        }
        __syncthreads();
    }

    // tot = fl(P0 + P1), lanewise rn adds == scalar
    #pragma unroll
    for (int i = 0; i < 8; i++)
        #pragma unroll
        for (int j = 0; j < 4; j++)
            ADD2(tot[i][j], tot[i][j], acc[i][j]);

    float4 bev0 = *(const float4*)(benc + n0 + tx4);
    float4 bev1 = *(const float4*)(benc + n0 + 64 + tx4);
    #pragma unroll
    for (int i = 0; i < 8; i++) {
        size_t row = (size_t)(m0 + ty8 + i);
        float4 o0, o1;
        o0.x = fmaxf(f2lo(tot[i][0]) + bev0.x, 0.f);
        o0.y = fmaxf(f2hi(tot[i][0]) + bev0.y, 0.f);
        o0.z = fmaxf(f2lo(tot[i][1]) + bev0.z, 0.f);
        o0.w = fmaxf(f2hi(tot[i][1]) + bev0.w, 0.f);
        o1.x = fmaxf(f2lo(tot[i][2]) + bev1.x, 0.f);
        o1.y = fmaxf(f2hi(tot[i][2]) + bev1.y, 0.f);
        o1.z = fmaxf(f2lo(tot[i][3]) + bev1.z, 0.f);
        o1.w = fmaxf(f2hi(tot[i][3]) + bev1.w, 0.f);
        *(float4*)(C + row * N_LAT + n0 + tx4)      = o0;
        *(float4*)(C + row * N_LAT + n0 + 64 + tx4) = o1;
    }
}

// ============================================================
// top-k per row (unchanged, passing)
// ============================================================
#define CAP_B 4096
#define TOPK_SMEM ((32768 + 2048 + CAP_B) * 4)

__global__ void topk_kernel(const float* __restrict__ feat,
                            float* __restrict__ p_ta, float* __restrict__ p_ti)
{
    extern __shared__ uint32_t dyn[];
    uint32_t* sv   = dyn;
    uint32_t* hist = sv + 32768;
    int*      listB = (int*)(hist + 2048);

    __shared__ int   csum[256];
    __shared__ int   red[256];
    __shared__ float pv[64];
    __shared__ int   pi[64];
    __shared__ int   listA[64];
    __shared__ int   tiesel[64];
    __shared__ uint32_t s_prefix;
    __shared__ int   s_kr, s_cntA, s_cntB, s_last;

    int tid = threadIdx.x;
    int row = blockIdx.x;

    const float4* src = (const float4*)(feat + (size_t)row * N_LAT);
    uint4* dst = (uint4*)sv;
    for (int i = tid; i < N_LAT / 4; i += 256) {
        float4 v = src[i];
        uint4 u;
        u.x = __float_as_uint(v.x); u.y = __float_as_uint(v.y);
        u.z = __float_as_uint(v.z); u.w = __float_as_uint(v.w);
        dst[i] = u;
    }
    __syncthreads();

    uint32_t prefix = 0;
    int Kr = TOPK;
    const int SH[3] = {21, 10, 0};
    const int NB[3] = {11, 11, 10};

    for (int lvl = 0; lvl < 3; lvl++) {
        int sh = SH[lvl], nbits = NB[lvl];
        int nbins = 1 << nbits;
        uint32_t mask = (uint32_t)(nbins - 1);
        int hib = sh + nbits;
        for (int i = tid; i < nbins; i += 256) hist[i] = 0;
        __syncthreads();
        int zloc = 0;
        for (int i = tid; i < N_LAT; i += 256) {
            uint32_t u = sv[i];
            bool match = (lvl == 0) || ((u >> hib) == prefix);
            if (match) {
                if (u == 0u) zloc++;
                else atomicAdd(&hist[(u >> sh) & mask], 1u);
            }
        }
        if (zloc) atomicAdd(&hist[0], (uint32_t)zloc);
        __syncthreads();
        int nch = nbins >> 3;
        if (tid < nch) {
            int s = 0;
            #pragma unroll
            for (int j = 0; j < 8; j++) s += (int)hist[tid * 8 + j];
            csum[tid] = s;
        }
        __syncthreads();
        if (tid == 0) {
            int acc = 0, c = nch - 1;
            for (; c > 0; c--) {
                if (acc + csum[c] >= Kr) break;
                acc += csum[c];
            }
            int b = c * 8 + 7;
            for (; b > c * 8; b--) {
                int h = (int)hist[b];
                if (acc + h >= Kr) break;
                acc += h;
            }
            s_prefix = (prefix << nbits) | (uint32_t)b;
            s_kr = Kr - acc;
        }
        __syncthreads();
        prefix = s_prefix;
        Kr = s_kr;
        __syncthreads();
    }

    uint32_t T = prefix;
    int Need = Kr;
    if (tid == 0) { s_cntA = 0; s_cntB = 0; }
    __syncthreads();
    for (int i = tid; i < N_LAT; i += 256) {
        uint32_t u = sv[i];
        if (u > T) {
            int p = atomicAdd(&s_cntA, 1);
            if (p < 64) listA[p] = i;
        } else if (u == T) {
            int p = atomicAdd(&s_cntB, 1);
            if (p < CAP_B) listB[p] = i;
        }
    }
    __syncthreads();
    int cA = s_cntA, cB = s_cntB;

    int last = -1;
    for (int s = 0; s < Need; s++) {
        int loc = 0x7FFFFFFF;
        if (cB <= CAP_B) {
            for (int i = tid; i < cB; i += 256) {
                int ix = listB[i];
                if (ix > last && ix < loc) loc = ix;
            }
        } else {
            for (int i = tid; i < N_LAT; i += 256) {
                if (sv[i] == T && i > last && i < loc) loc = i;
            }
        }
        red[tid] = loc;
        __syncthreads();
        for (int st = 128; st > 0; st >>= 1) {
            if (tid < st) red[tid] = min(red[tid], red[tid + st]);
            __syncthreads();
        }
        if (tid == 0) { tiesel[s] = red[0]; s_last = red[0]; }
        __syncthreads();
        last = s_last;
    }

    if (tid < 64) {
        float v; int ix;
        if (tid < cA) { ix = listA[tid]; v = __uint_as_float(sv[ix]); }
        else          { ix = tiesel[tid - cA]; v = __uint_as_float(T); }
        pv[tid] = v; pi[tid] = ix;
    }
    __syncthreads();
    if (tid < 64) {
        float v = pv[tid]; int ix = pi[tid];
        int rank = 0;
        #pragma unroll 8
        for (int j = 0; j < 64; j++) {
            float vj = pv[j]; int ij = pi[j];
            if (vj > v || (vj == v && ij < ix)) rank++;
        }
        size_t o = (size_t)row * TOPK + rank;
        g_top_val[o] = v;
        g_top_idx[o] = ix;
        if (p_ta) p_ta[o] = v;
        if (p_ti) p_ti[o] = (float)ix;
    }
}

// ============================================================
__global__ void decode_kernel(const float* __restrict__ X,
                              const float* __restrict__ Wd,
                              const float* __restrict__ bdec,
                              float* __restrict__ sae)
{
    __shared__ float sval[64];
    __shared__ int   sidx[64];
    __shared__ float red[256];
    int tid = threadIdx.x, row = blockIdx.x;
    if (tid < 64) {
        sval[tid] = g_top_val[row * TOPK + tid];
        sidx[tid] = g_top_idx[row * TOPK + tid];
    }
    __syncthreads();
    int d0 = tid * 4;
    float4 acc = *(const float4*)(bdec + d0);
    #pragma unroll 4
    for (int k = 0; k < TOPK; k++) {
        float a = sval[k];
        float4 w = *(const float4*)(Wd + (size_t)sidx[k] * D_DIM + d0);
        acc.x += a * w.x; acc.y += a * w.y; acc.z += a * w.z; acc.w += a * w.w;
    }
    size_t o = (size_t)row * D_DIM + d0;
    if (sae) *(float4*)(sae + o) = acc;
    float4 xv = *(const float4*)(X + o);
    float ex = acc.x - xv.x, ey = acc.y - xv.y, ez = acc.z - xv.z, ew = acc.w - xv.w;
    red[tid] = ex * ex + ey * ey + ez * ez + ew * ew;
    __syncthreads();
    for (int st = 128; st > 0; st >>= 1) {
        if (tid < st) red[tid] += red[tid + st];
        __syncthreads();
    }
    if (tid == 0) atomicAdd(&g_acc[0], red[0]);
}

// ============================================================
__global__ void finalize_kernel(float* __restrict__ p_sc) {
    __shared__ float red[256];
    int tid = threadIdx.x;
    float s = 0.f;
    for (int i = tid; i < D_DIM; i += 256) {
        float cs = g_colsum[i];
        s += cs * cs;
    }
    red[tid] = s;
    __syncthreads();
    for (int st = 128; st > 0; st >>= 1) {
        if (tid < st) red[tid] += red[tid + st];
        __syncthreads();
    }
    if (tid == 0) {
        float TV  = g_acc[1] - red[0] / (float)B_N;
        float SSE = g_acc[0];
        p_sc[0] = SSE / TV;
        p_sc[1] = 0.f;
        p_sc[2] = 0.f;
        p_sc[3] = 0.f;
        p_sc[4] = SSE / (float)B_N;
    }
}

// ============================================================
extern "C" void kernel_launch(void* const* d_in, const int* in_sizes, int n_in,
                              void* d_out, int out_size)
{
    const float *x = nullptr, *We = nullptr, *be = nullptr, *Wd = nullptr, *bd = nullptr;
    int big_seen = 0;
    for (int i = 0; i < n_in; i++) {
        int sz = in_sizes[i];
        const float* p = (const float*)d_in[i];
        if (sz == (int)SZ_SAE)          x = p;
        else if (sz == N_LAT * D_DIM)   { if (big_seen++ == 0) We = p; else Wd = p; }
        else if (sz == N_LAT)           be = p;
        else if (sz == D_DIM)           bd = p;
    }

    float* out = (float*)d_out;
    float *p_sae = nullptr, *p_feat = nullptr, *p_ta = nullptr, *p_ti = nullptr, *p_sc = nullptr;

    if ((size_t)out_size == TOTAL_FULL) {
        p_sae  = out;
        p_feat = out + SZ_SAE;
        p_ta   = out + SZ_SAE + SZ_FEAT;
        p_ti   = p_ta + SZ_TA;
        p_sc   = p_ti + SZ_TA;
    } else if ((size_t)out_size == TOTAL_NOFEAT) {
        p_sae = out;
        p_ta  = out + SZ_SAE;
        p_ti  = p_ta + SZ_TA;
        p_sc  = p_ti + SZ_TA;
    } else {
        p_sae = out;
    }

    if (!p_feat) {
        void* fp = nullptr;
        cudaGetSymbolAddress(&fp, g_feat_fallback);
        p_feat = (float*)fp;
    }

    init_kernel<<<1, 32>>>();
    xc_kernel<<<(B_N * D_DIM / 4) / 256, 256>>>(x, bd);
    colstats_kernel<<<D_DIM / 256, 256>>>(x);
    cudaFuncSetAttribute(encode_gemm, cudaFuncAttributeMaxDynamicSharedMemorySize, 65536);
    encode_gemm<<<dim3(B_N / 128, N_LAT / 128), 256, 65536>>>(We, be, p_feat);
    cudaFuncSetAttribute(topk_kernel, cudaFuncAttributeMaxDynamicSharedMemorySize, TOPK_SMEM);
    topk_kernel<<<B_N, 256, TOPK_SMEM>>>(p_feat, p_ta, p_ti);
    decode_kernel<<<B_N, 256>>>(x, Wd, bd, p_sae);
    if (p_sc) finalize_kernel<<<1, 256>>>(p_sc);
}

// round 12
// speedup vs baseline: 1.5542x; 1.0699x over previous
#include <cuda_runtime.h>
#include <cstdint>

#define B_N   4096
#define D_DIM 1024
#define N_LAT 32768
#define TOPK  64

// frozen arithmetic: 2 k-panels of 512, fresh acc, fl(P0+P1), +b_enc, relu
#define NT 32                 // k-tiles of 32
#define TILES_PER_CHUNK 16    // 512/32

// ---- output layout (flattened tuple concat, f32) ----
#define SZ_SAE  ((size_t)B_N * D_DIM)
#define SZ_FEAT ((size_t)B_N * N_LAT)
#define SZ_TA   ((size_t)B_N * TOPK)
#define TOTAL_FULL (SZ_SAE + SZ_FEAT + SZ_TA + SZ_TA + 5)
#define TOTAL_NOFEAT (SZ_SAE + SZ_TA + SZ_TA + 5)

// ---- scratch ----
__device__ float g_top_val[B_N * TOPK];
__device__ int   g_top_idx[B_N * TOPK];
__device__ float g_colsum[D_DIM];
__device__ float g_acc[4];
__device__ float g_xc[(size_t)B_N * D_DIM];          // x - b_dec
__device__ float g_feat_fallback[(size_t)B_N * N_LAT];

#define FMA2(c,a,b) asm("fma.rn.f32x2 %0, %1, %2, %3;" : "=l"(c) : "l"(a), "l"(b), "l"(c))
#define ADD2(c,a,b) asm("add.rn.f32x2 %0, %1, %2;"     : "=l"(c) : "l"(a), "l"(b))
// register dup: (f,f) 64-bit pair, 1 ALU instr (alu pipe idle; L1 is the bottleneck)
#define PAIR(d,f)   asm("mov.b64 %0, {%1, %1};"        : "=l"(d) : "r"(__float_as_uint(f)))

__device__ __forceinline__ float f2lo(unsigned long long v) { return __uint_as_float((unsigned)v); }
__device__ __forceinline__ float f2hi(unsigned long long v) { return __uint_as_float((unsigned)(v >> 32)); }
__device__ __forceinline__ unsigned long long packf2(float lo, float hi) {
    return ((unsigned long long)__float_as_uint(hi) << 32) | __float_as_uint(lo);
}

// ============================================================
__global__ void init_kernel() {
    int t = threadIdx.x;
    if (t < 4) g_acc[t] = 0.0f;
}

// xc = x - b_dec (elementwise, same fl as reference)
__global__ void xc_kernel(const float* __restrict__ X, const float* __restrict__ bdec) {
    int i = blockIdx.x * blockDim.x + threadIdx.x;      // float4 index
    float4 v = ((const float4*)X)[i];
    float4 d = ((const float4*)bdec)[i & 255];
    v.x -= d.x; v.y -= d.y; v.z -= d.z; v.w -= d.w;
    ((float4*)g_xc)[i] = v;
}

// ============================================================
__global__ void colstats_kernel(const float* __restrict__ X) {
    int c = blockIdx.x * blockDim.x + threadIdx.x;
    float s = 0.f, q = 0.f;
    #pragma unroll 4
    for (int n = 0; n < B_N; n++) {
        float v = X[(size_t)n * D_DIM + c];
        s += v;
        q += v * v;
    }
    g_colsum[c] = s;
    atomicAdd(&g_acc[1], q);
}

// ============================================================
// encode GEMM, FFMA2, 512 threads, tile 256m x 128n, 8m x 8n per thread.
// 16 warps/SM for latency hiding. P0 panel spilled RAW to C at the k=512
// chunk boundary (f32 bits exact), read back at the end: tot = fl(P0+P1).
// A plain floats [k][256]; (a,a) pairs built in registers. BK=32, 96KB smem.
// Per-element k-order preserved exactly.
// ============================================================
__global__ __launch_bounds__(512, 1)
void encode_gemm(const float* __restrict__ W,
                 const float* __restrict__ benc,
                 float* __restrict__ C)
{
    extern __shared__ char smem_raw[];
    float* As = (float*)smem_raw;                 // [2][32][256] = 64KB
    float* Bs = (float*)(smem_raw + 65536);       // [2][32][128] = 32KB

    int tid = threadIdx.x;
    int tx  = tid & 15;          // n group: cols tx*4 and 64+tx*4
    int ty  = tid >> 4;          // m group 0..31: rows ty*8..ty*8+7
    int ty8 = ty * 8;
    int tx4 = tx * 4;
    int m0 = blockIdx.x * 256;
    int n0 = blockIdx.y * 128;

    // loaders: A rows 256 (16 floats/thread), B rows 128 (8 floats/thread)
    int ar = tid >> 1;           // 0..255
    int ac = (tid & 1) << 4;     // 0 or 16
    int br = tid >> 2;           // 0..127
    int bc = (tid & 3) << 3;     // 0,8,16,24

    const float* aptr = g_xc + (size_t)(m0 + ar) * D_DIM + ac;
    const float* bptr = W    + (size_t)(n0 + br) * D_DIM + bc;

    float4 ra[4], rb[2];

    // prologue: tile 0 -> stage 0
    #pragma unroll
    for (int q = 0; q < 4; q++) ra[q] = *(const float4*)(aptr + q * 4);
    #pragma unroll
    for (int q = 0; q < 2; q++) rb[q] = *(const float4*)(bptr + q * 4);
    #pragma unroll
    for (int q = 0; q < 4; q++) {
        const float* rf = (const float*)&ra[q];
        #pragma unroll
        for (int j = 0; j < 4; j++) As[(ac + q * 4 + j) * 256 + ar] = rf[j];
    }
    #pragma unroll
    for (int q = 0; q < 2; q++) {
        const float* bf = (const float*)&rb[q];
        #pragma unroll
        for (int j = 0; j < 4; j++) Bs[(bc + q * 4 + j) * 128 + br] = bf[j];
    }
    // prefetch tile 1
    #pragma unroll
    for (int q = 0; q < 4; q++) ra[q] = *(const float4*)(aptr + 32 + q * 4);
    #pragma unroll
    for (int q = 0; q < 2; q++) rb[q] = *(const float4*)(bptr + 32 + q * 4);
    __syncthreads();

    unsigned long long acc[8][4];
    #pragma unroll
    for (int i = 0; i < 8; i++)
        #pragma unroll
        for (int j = 0; j < 4; j++) acc[i][j] = 0ULL;

    for (int t = 0; t < NT; t++) {
        int s = t & 1;
        const float* As_s = As + s * 8192;
        const float* Bs_s = Bs + s * 4096;
        #pragma unroll
        for (int kk = 0; kk < 32; kk++) {
            float4 a03 = *(const float4*)(As_s + kk * 256 + ty8);
            float4 a47 = *(const float4*)(As_s + kk * 256 + ty8 + 4);
            ulonglong2 bl = *(const ulonglong2*)(Bs_s + kk * 128 + tx4);
            ulonglong2 bh = *(const ulonglong2*)(Bs_s + kk * 128 + 64 + tx4);
            unsigned long long a2;
            PAIR(a2, a03.x);
            FMA2(acc[0][0], a2, bl.x); FMA2(acc[0][1], a2, bl.y);
            FMA2(acc[0][2], a2, bh.x); FMA2(acc[0][3], a2, bh.y);
            PAIR(a2, a03.y);
            FMA2(acc[1][0], a2, bl.x); FMA2(acc[1][1], a2, bl.y);
            FMA2(acc[1][2], a2, bh.x); FMA2(acc[1][3], a2, bh.y);
            PAIR(a2, a03.z);
            FMA2(acc[2][0], a2, bl.x); FMA2(acc[2][1], a2, bl.y);
            FMA2(acc[2][2], a2, bh.x); FMA2(acc[2][3], a2, bh.y);
            PAIR(a2, a03.w);
            FMA2(acc[3][0], a2, bl.x); FMA2(acc[3][1], a2, bl.y);
            FMA2(acc[3][2], a2, bh.x); FMA2(acc[3][3], a2, bh.y);
            PAIR(a2, a47.x);
            FMA2(acc[4][0], a2, bl.x); FMA2(acc[4][1], a2, bl.y);
            FMA2(acc[4][2], a2, bh.x); FMA2(acc[4][3], a2, bh.y);
            PAIR(a2, a47.y);
            FMA2(acc[5][0], a2, bl.x); FMA2(acc[5][1], a2, bl.y);
            FMA2(acc[5][2], a2, bh.x); FMA2(acc[5][3], a2, bh.y);
            PAIR(a2, a47.z);
            FMA2(acc[6][0], a2, bl.x); FMA2(acc[6][1], a2, bl.y);
            FMA2(acc[6][2], a2, bh.x); FMA2(acc[6][3], a2, bh.y);
            PAIR(a2, a47.w);
            FMA2(acc[7][0], a2, bl.x); FMA2(acc[7][1], a2, bl.y);
            FMA2(acc[7][2], a2, bh.x); FMA2(acc[7][3], a2, bh.y);
        }

        // chunk boundary: spill raw P0 to C (exact f32 bits), restart acc
        if (t == TILES_PER_CHUNK - 1) {
            #pragma unroll
            for (int i = 0; i < 8; i++) {
                size_t row = (size_t)(m0 + ty8 + i);
                float4 p0, p1;
                p0.x = f2lo(acc[i][0]); p0.y = f2hi(acc[i][0]);
                p0.z = f2lo(acc[i][1]); p0.w = f2hi(acc[i][1]);
                p1.x = f2lo(acc[i][2]); p1.y = f2hi(acc[i][2]);
                p1.z = f2lo(acc[i][3]); p1.w = f2hi(acc[i][3]);
                *(float4*)(C + row * N_LAT + n0 + tx4)      = p0;
                *(float4*)(C + row * N_LAT + n0 + 64 + tx4) = p1;
                #pragma unroll
                for (int j = 0; j < 4; j++) acc[i][j] = 0ULL;
            }
        }

        if (t < NT - 1) {
            int sn = (t + 1) & 1;
            float* As_n = As + sn * 8192;
            float* Bs_n = Bs + sn * 4096;
            #pragma unroll
            for (int q = 0; q < 4; q++) {
                const float* rf = (const float*)&ra[q];
                #pragma unroll
                for (int j = 0; j < 4; j++) As_n[(ac + q * 4 + j) * 256 + ar] = rf[j];
            }
            #pragma unroll
            for (int q = 0; q < 2; q++) {
                const float* bf = (const float*)&rb[q];
                #pragma unroll
                for (int j = 0; j < 4; j++) Bs_n[(bc + q * 4 + j) * 128 + br] = bf[j];
            }
            if (t < NT - 2) {
                #pragma unroll
                for (int q = 0; q < 4; q++) ra[q] = *(const float4*)(aptr + (t + 2) * 32 + q * 4);
                #pragma unroll
                for (int q = 0; q < 2; q++) rb[q] = *(const float4*)(bptr + (t + 2) * 32 + q * 4);
            }
        }
        __syncthreads();
    }

    // readback P0, tot = fl(P0 + P1) lanewise, +b_enc, relu, final store
    float4 bev0 = *(const float4*)(benc + n0 + tx4);
    float4 bev1 = *(const float4*)(benc + n0 + 64 + tx4);
    #pragma unroll
    for (int i = 0; i < 8; i++) {
        size_t row = (size_t)(m0 + ty8 + i);
        float4 p0 = *(const float4*)(C + row * N_LAT + n0 + tx4);
        float4 p1 = *(const float4*)(C + row * N_LAT + n0 + 64 + tx4);
        unsigned long long s0, s1, s2, s3;
        s0 = packf2(p0.x, p0.y); s1 = packf2(p0.z, p0.w);
        s2 = packf2(p1.x, p1.y); s3 = packf2(p1.z, p1.w);
        ADD2(s0, s0, acc[i][0]);
        ADD2(s1, s1, acc[i][1]);
        ADD2(s2, s2, acc[i][2]);
        ADD2(s3, s3, acc[i][3]);
        float4 o0, o1;
        o0.x = fmaxf(f2lo(s0) + bev0.x, 0.f);
        o0.y = fmaxf(f2hi(s0) + bev0.y, 0.f);
        o0.z = fmaxf(f2lo(s1) + bev0.z, 0.f);
        o0.w = fmaxf(f2hi(s1) + bev0.w, 0.f);
        o1.x = fmaxf(f2lo(s2) + bev1.x, 0.f);
        o1.y = fmaxf(f2hi(s2) + bev1.y, 0.f);
        o1.z = fmaxf(f2lo(s3) + bev1.z, 0.f);
        o1.w = fmaxf(f2hi(s3) + bev1.w, 0.f);
        *(float4*)(C + row * N_LAT + n0 + tx4)      = o0;
        *(float4*)(C + row * N_LAT + n0 + 64 + tx4) = o1;
    }
}

// ============================================================
// top-k per row (unchanged, passing)
// ============================================================
#define CAP_B 4096
#define TOPK_SMEM ((32768 + 2048 + CAP_B) * 4)

__global__ void topk_kernel(const float* __restrict__ feat,
                            float* __restrict__ p_ta, float* __restrict__ p_ti)
{
    extern __shared__ uint32_t dyn[];
    uint32_t* sv   = dyn;
    uint32_t* hist = sv + 32768;
    int*      listB = (int*)(hist + 2048);

    __shared__ int   csum[256];
    __shared__ int   red[256];
    __shared__ float pv[64];
    __shared__ int   pi[64];
    __shared__ int   listA[64];
    __shared__ int   tiesel[64];
    __shared__ uint32_t s_prefix;
    __shared__ int   s_kr, s_cntA, s_cntB, s_last;

    int tid = threadIdx.x;
    int row = blockIdx.x;

    const float4* src = (const float4*)(feat + (size_t)row * N_LAT);
    uint4* dst = (uint4*)sv;
    for (int i = tid; i < N_LAT / 4; i += 256) {
        float4 v = src[i];
        uint4 u;
        u.x = __float_as_uint(v.x); u.y = __float_as_uint(v.y);
        u.z = __float_as_uint(v.z); u.w = __float_as_uint(v.w);
        dst[i] = u;
    }
    __syncthreads();

    uint32_t prefix = 0;
    int Kr = TOPK;
    const int SH[3] = {21, 10, 0};
    const int NB[3] = {11, 11, 10};

    for (int lvl = 0; lvl < 3; lvl++) {
        int sh = SH[lvl], nbits = NB[lvl];
        int nbins = 1 << nbits;
        uint32_t mask = (uint32_t)(nbins - 1);
        int hib = sh + nbits;
        for (int i = tid; i < nbins; i += 256) hist[i] = 0;
        __syncthreads();
        int zloc = 0;
        for (int i = tid; i < N_LAT; i += 256) {
            uint32_t u = sv[i];
            bool match = (lvl == 0) || ((u >> hib) == prefix);
            if (match) {
                if (u == 0u) zloc++;
                else atomicAdd(&hist[(u >> sh) & mask], 1u);
            }
        }
        if (zloc) atomicAdd(&hist[0], (uint32_t)zloc);
        __syncthreads();
        int nch = nbins >> 3;
        if (tid < nch) {
            int s = 0;
            #pragma unroll
            for (int j = 0; j < 8; j++) s += (int)hist[tid * 8 + j];
            csum[tid] = s;
        }
        __syncthreads();
        if (tid == 0) {
            int acc = 0, c = nch - 1;
            for (; c > 0; c--) {
                if (acc + csum[c] >= Kr) break;
                acc += csum[c];
            }
            int b = c * 8 + 7;
            for (; b > c * 8; b--) {
                int h = (int)hist[b];
                if (acc + h >= Kr) break;
                acc += h;
            }
            s_prefix = (prefix << nbits) | (uint32_t)b;
            s_kr = Kr - acc;
        }
        __syncthreads();
        prefix = s_prefix;
        Kr = s_kr;
        __syncthreads();
    }

    uint32_t T = prefix;
    int Need = Kr;
    if (tid == 0) { s_cntA = 0; s_cntB = 0; }
    __syncthreads();
    for (int i = tid; i < N_LAT; i += 256) {
        uint32_t u = sv[i];
        if (u > T) {
            int p = atomicAdd(&s_cntA, 1);
            if (p < 64) listA[p] = i;
        } else if (u == T) {
            int p = atomicAdd(&s_cntB, 1);
            if (p < CAP_B) listB[p] = i;
        }
    }
    __syncthreads();
    int cA = s_cntA, cB = s_cntB;

    int last = -1;
    for (int s = 0; s < Need; s++) {
        int loc = 0x7FFFFFFF;
        if (cB <= CAP_B) {
            for (int i = tid; i < cB; i += 256) {
                int ix = listB[i];
                if (ix > last && ix < loc) loc = ix;
            }
        } else {
            for (int i = tid; i < N_LAT; i += 256) {
                if (sv[i] == T && i > last && i < loc) loc = i;
            }
        }
        red[tid] = loc;
        __syncthreads();
        for (int st = 128; st > 0; st >>= 1) {
            if (tid < st) red[tid] = min(red[tid], red[tid + st]);
            __syncthreads();
        }
        if (tid == 0) { tiesel[s] = red[0]; s_last = red[0]; }
        __syncthreads();
        last = s_last;
    }

    if (tid < 64) {
        float v; int ix;
        if (tid < cA) { ix = listA[tid]; v = __uint_as_float(sv[ix]); }
        else          { ix = tiesel[tid - cA]; v = __uint_as_float(T); }
        pv[tid] = v; pi[tid] = ix;
    }
    __syncthreads();
    if (tid < 64) {
        float v = pv[tid]; int ix = pi[tid];
        int rank = 0;
        #pragma unroll 8
        for (int j = 0; j < 64; j++) {
            float vj = pv[j]; int ij = pi[j];
            if (vj > v || (vj == v && ij < ix)) rank++;
        }
        size_t o = (size_t)row * TOPK + rank;
        g_top_val[o] = v;
        g_top_idx[o] = ix;
        if (p_ta) p_ta[o] = v;
        if (p_ti) p_ti[o] = (float)ix;
    }
}

// ============================================================
__global__ void decode_kernel(const float* __restrict__ X,
                              const float* __restrict__ Wd,
                              const float* __restrict__ bdec,
                              float* __restrict__ sae)
{
    __shared__ float sval[64];
    __shared__ int   sidx[64];
    __shared__ float red[256];
    int tid = threadIdx.x, row = blockIdx.x;
    if (tid < 64) {
        sval[tid] = g_top_val[row * TOPK + tid];
        sidx[tid] = g_top_idx[row * TOPK + tid];
    }
    __syncthreads();
    int d0 = tid * 4;
    float4 acc = *(const float4*)(bdec + d0);
    #pragma unroll 4
    for (int k = 0; k < TOPK; k++) {
        float a = sval[k];
        float4 w = *(const float4*)(Wd + (size_t)sidx[k] * D_DIM + d0);
        acc.x += a * w.x; acc.y += a * w.y; acc.z += a * w.z; acc.w += a * w.w;
    }
    size_t o = (size_t)row * D_DIM + d0;
    if (sae) *(float4*)(sae + o) = acc;
    float4 xv = *(const float4*)(X + o);
    float ex = acc.x - xv.x, ey = acc.y - xv.y, ez = acc.z - xv.z, ew = acc.w - xv.w;
    red[tid] = ex * ex + ey * ey + ez * ez + ew * ew;
    __syncthreads();
    for (int st = 128; st > 0; st >>= 1) {
        if (tid < st) red[tid] += red[tid + st];
        __syncthreads();
    }
    if (tid == 0) atomicAdd(&g_acc[0], red[0]);
}

// ============================================================
__global__ void finalize_kernel(float* __restrict__ p_sc) {
    __shared__ float red[256];
    int tid = threadIdx.x;
    float s = 0.f;
    for (int i = tid; i < D_DIM; i += 256) {
        float cs = g_colsum[i];
        s += cs * cs;
    }
    red[tid] = s;
    __syncthreads();
    for (int st = 128; st > 0; st >>= 1) {
        if (tid < st) red[tid] += red[tid + st];
        __syncthreads();
    }
    if (tid == 0) {
        float TV  = g_acc[1] - red[0] / (float)B_N;
        float SSE = g_acc[0];
        p_sc[0] = SSE / TV;
        p_sc[1] = 0.f;
        p_sc[2] = 0.f;
        p_sc[3] = 0.f;
        p_sc[4] = SSE / (float)B_N;
    }
}

// ============================================================
extern "C" void kernel_launch(void* const* d_in, const int* in_sizes, int n_in,
                              void* d_out, int out_size)
{
    const float *x = nullptr, *We = nullptr, *be = nullptr, *Wd = nullptr, *bd = nullptr;
    int big_seen = 0;
    for (int i = 0; i < n_in; i++) {
        int sz = in_sizes[i];
        const float* p = (const float*)d_in[i];
        if (sz == (int)SZ_SAE)          x = p;
        else if (sz == N_LAT * D_DIM)   { if (big_seen++ == 0) We = p; else Wd = p; }
        else if (sz == N_LAT)           be = p;
        else if (sz == D_DIM)           bd = p;
    }

    float* out = (float*)d_out;
    float *p_sae = nullptr, *p_feat = nullptr, *p_ta = nullptr, *p_ti = nullptr, *p_sc = nullptr;

    if ((size_t)out_size == TOTAL_FULL) {
        p_sae  = out;
        p_feat = out + SZ_SAE;
        p_ta   = out + SZ_SAE + SZ_FEAT;
        p_ti   = p_ta + SZ_TA;
        p_sc   = p_ti + SZ_TA;
    } else if ((size_t)out_size == TOTAL_NOFEAT) {
        p_sae = out;
        p_ta  = out + SZ_SAE;
        p_ti  = p_ta + SZ_TA;
        p_sc  = p_ti + SZ_TA;
    } else {
        p_sae = out;
    }

    if (!p_feat) {
        void* fp = nullptr;
        cudaGetSymbolAddress(&fp, g_feat_fallback);
        p_feat = (float*)fp;
    }

    init_kernel<<<1, 32>>>();
    xc_kernel<<<(B_N * D_DIM / 4) / 256, 256>>>(x, bd);
    colstats_kernel<<<D_DIM / 256, 256>>>(x);
    cudaFuncSetAttribute(encode_gemm, cudaFuncAttributeMaxDynamicSharedMemorySize, 98304);
    encode_gemm<<<dim3(B_N / 256, N_LAT / 128), 512, 98304>>>(We, be, p_feat);
    cudaFuncSetAttribute(topk_kernel, cudaFuncAttributeMaxDynamicSharedMemorySize, TOPK_SMEM);
    topk_kernel<<<B_N, 256, TOPK_SMEM>>>(p_feat, p_ta, p_ti);
    decode_kernel<<<B_N, 256>>>(x, Wd, bd, p_sae);
    if (p_sc) finalize_kernel<<<1, 256>>>(p_sc);
}

// round 13
// speedup vs baseline: 1.6422x; 1.0567x over previous
#include <cuda_runtime.h>
#include <cstdint>

#define B_N   4096
#define D_DIM 1024
#define N_LAT 32768
#define TOPK  64

// frozen arithmetic: 2 k-panels of 512, fresh acc, fl(P0+P1), +b_enc, relu
#define NT 32                 // k-tiles of 32
#define TILES_PER_CHUNK 16    // 512/32

// ---- output layout (flattened tuple concat, f32) ----
#define SZ_SAE  ((size_t)B_N * D_DIM)
#define SZ_FEAT ((size_t)B_N * N_LAT)
#define SZ_TA   ((size_t)B_N * TOPK)
#define TOTAL_FULL (SZ_SAE + SZ_FEAT + SZ_TA + SZ_TA + 5)
#define TOTAL_NOFEAT (SZ_SAE + SZ_TA + SZ_TA + 5)

// ---- scratch ----
__device__ float g_top_val[B_N * TOPK];
__device__ int   g_top_idx[B_N * TOPK];
__device__ float g_colsum[D_DIM];
__device__ float g_acc[4];
__device__ float g_xc[(size_t)B_N * D_DIM];          // x - b_dec
__device__ float g_feat_fallback[(size_t)B_N * N_LAT];

#define FMA2(c,a,b) asm("fma.rn.f32x2 %0, %1, %2, %3;" : "=l"(c) : "l"(a), "l"(b), "l"(c))
#define ADD2(c,a,b) asm("add.rn.f32x2 %0, %1, %2;"     : "=l"(c) : "l"(a), "l"(b))
#define PAIR(d,f)   asm("mov.b64 %0, {%1, %1};"        : "=l"(d) : "r"(__float_as_uint(f)))

__device__ __forceinline__ float f2lo(unsigned long long v) { return __uint_as_float((unsigned)v); }
__device__ __forceinline__ float f2hi(unsigned long long v) { return __uint_as_float((unsigned)(v >> 32)); }
__device__ __forceinline__ unsigned long long packf2(float lo, float hi) {
    return ((unsigned long long)__float_as_uint(hi) << 32) | __float_as_uint(lo);
}

// ============================================================
__global__ void init_kernel() {
    int i = blockIdx.x * 256 + threadIdx.x;
    if (i < D_DIM) g_colsum[i] = 0.0f;
    if (i < 4) g_acc[i] = 0.0f;
}

// xc = x - b_dec (elementwise, same fl as reference)
__global__ void xc_kernel(const float* __restrict__ X, const float* __restrict__ bdec) {
    int i = blockIdx.x * blockDim.x + threadIdx.x;      // float4 index
    float4 v = ((const float4*)X)[i];
    float4 d = ((const float4*)bdec)[i & 255];
    v.x -= d.x; v.y -= d.y; v.z -= d.z; v.w -= d.w;
    ((float4*)g_xc)[i] = v;
}

// ============================================================
// column stats, parallel over row chunks: grid (4, 16), 256 thr
__global__ void colstats_kernel(const float* __restrict__ X) {
    __shared__ float redq[256];
    int c  = blockIdx.x * 256 + threadIdx.x;   // column 0..1023
    int r0 = blockIdx.y * 256;                 // row chunk
    float s = 0.f, q = 0.f;
    #pragma unroll 4
    for (int n = r0; n < r0 + 256; n++) {
        float v = X[(size_t)n * D_DIM + c];
        s += v;
        q += v * v;
    }
    atomicAdd(&g_colsum[c], s);
    redq[threadIdx.x] = q;
    __syncthreads();
    for (int st = 128; st > 0; st >>= 1) {
        if (threadIdx.x < st) redq[threadIdx.x] += redq[threadIdx.x + st];
        __syncthreads();
    }
    if (threadIdx.x == 0) atomicAdd(&g_acc[1], redq[0]);
}

// ============================================================
// encode GEMM (unchanged from R12 winner)
// ============================================================
__global__ __launch_bounds__(512, 1)
void encode_gemm(const float* __restrict__ W,
                 const float* __restrict__ benc,
                 float* __restrict__ C)
{
    extern __shared__ char smem_raw[];
    float* As = (float*)smem_raw;                 // [2][32][256] = 64KB
    float* Bs = (float*)(smem_raw + 65536);       // [2][32][128] = 32KB

    int tid = threadIdx.x;
    int tx  = tid & 15;
    int ty  = tid >> 4;
    int ty8 = ty * 8;
    int tx4 = tx * 4;
    int m0 = blockIdx.x * 256;
    int n0 = blockIdx.y * 128;

    int ar = tid >> 1;
    int ac = (tid & 1) << 4;
    int br = tid >> 2;
    int bc = (tid & 3) << 3;

    const float* aptr = g_xc + (size_t)(m0 + ar) * D_DIM + ac;
    const float* bptr = W    + (size_t)(n0 + br) * D_DIM + bc;

    float4 ra[4], rb[2];

    #pragma unroll
    for (int q = 0; q < 4; q++) ra[q] = *(const float4*)(aptr + q * 4);
    #pragma unroll
    for (int q = 0; q < 2; q++) rb[q] = *(const float4*)(bptr + q * 4);
    #pragma unroll
    for (int q = 0; q < 4; q++) {
        const float* rf = (const float*)&ra[q];
        #pragma unroll
        for (int j = 0; j < 4; j++) As[(ac + q * 4 + j) * 256 + ar] = rf[j];
    }
    #pragma unroll
    for (int q = 0; q < 2; q++) {
        const float* bf = (const float*)&rb[q];
        #pragma unroll
        for (int j = 0; j < 4; j++) Bs[(bc + q * 4 + j) * 128 + br] = bf[j];
    }
    #pragma unroll
    for (int q = 0; q < 4; q++) ra[q] = *(const float4*)(aptr + 32 + q * 4);
    #pragma unroll
    for (int q = 0; q < 2; q++) rb[q] = *(const float4*)(bptr + 32 + q * 4);
    __syncthreads();

    unsigned long long acc[8][4];
    #pragma unroll
    for (int i = 0; i < 8; i++)
        #pragma unroll
        for (int j = 0; j < 4; j++) acc[i][j] = 0ULL;

    for (int t = 0; t < NT; t++) {
        int s = t & 1;
        const float* As_s = As + s * 8192;
        const float* Bs_s = Bs + s * 4096;
        #pragma unroll
        for (int kk = 0; kk < 32; kk++) {
            float4 a03 = *(const float4*)(As_s + kk * 256 + ty8);
            float4 a47 = *(const float4*)(As_s + kk * 256 + ty8 + 4);
            ulonglong2 bl = *(const ulonglong2*)(Bs_s + kk * 128 + tx4);
            ulonglong2 bh = *(const ulonglong2*)(Bs_s + kk * 128 + 64 + tx4);
            unsigned long long a2;
            PAIR(a2, a03.x);
            FMA2(acc[0][0], a2, bl.x); FMA2(acc[0][1], a2, bl.y);
            FMA2(acc[0][2], a2, bh.x); FMA2(acc[0][3], a2, bh.y);
            PAIR(a2, a03.y);
            FMA2(acc[1][0], a2, bl.x); FMA2(acc[1][1], a2, bl.y);
            FMA2(acc[1][2], a2, bh.x); FMA2(acc[1][3], a2, bh.y);
            PAIR(a2, a03.z);
            FMA2(acc[2][0], a2, bl.x); FMA2(acc[2][1], a2, bl.y);
            FMA2(acc[2][2], a2, bh.x); FMA2(acc[2][3], a2, bh.y);
            PAIR(a2, a03.w);
            FMA2(acc[3][0], a2, bl.x); FMA2(acc[3][1], a2, bl.y);
            FMA2(acc[3][2], a2, bh.x); FMA2(acc[3][3], a2, bh.y);
            PAIR(a2, a47.x);
            FMA2(acc[4][0], a2, bl.x); FMA2(acc[4][1], a2, bl.y);
            FMA2(acc[4][2], a2, bh.x); FMA2(acc[4][3], a2, bh.y);
            PAIR(a2, a47.y);
            FMA2(acc[5][0], a2, bl.x); FMA2(acc[5][1], a2, bl.y);
            FMA2(acc[5][2], a2, bh.x); FMA2(acc[5][3], a2, bh.y);
            PAIR(a2, a47.z);
            FMA2(acc[6][0], a2, bl.x); FMA2(acc[6][1], a2, bl.y);
            FMA2(acc[6][2], a2, bh.x); FMA2(acc[6][3], a2, bh.y);
            PAIR(a2, a47.w);
            FMA2(acc[7][0], a2, bl.x); FMA2(acc[7][1], a2, bl.y);
            FMA2(acc[7][2], a2, bh.x); FMA2(acc[7][3], a2, bh.y);
        }

        if (t == TILES_PER_CHUNK - 1) {
            #pragma unroll
            for (int i = 0; i < 8; i++) {
                size_t row = (size_t)(m0 + ty8 + i);
                float4 p0, p1;
                p0.x = f2lo(acc[i][0]); p0.y = f2hi(acc[i][0]);
                p0.z = f2lo(acc[i][1]); p0.w = f2hi(acc[i][1]);
                p1.x = f2lo(acc[i][2]); p1.y = f2hi(acc[i][2]);
                p1.z = f2lo(acc[i][3]); p1.w = f2hi(acc[i][3]);
                *(float4*)(C + row * N_LAT + n0 + tx4)      = p0;
                *(float4*)(C + row * N_LAT + n0 + 64 + tx4) = p1;
                #pragma unroll
                for (int j = 0; j < 4; j++) acc[i][j] = 0ULL;
            }
        }

        if (t < NT - 1) {
            int sn = (t + 1) & 1;
            float* As_n = As + sn * 8192;
            float* Bs_n = Bs + sn * 4096;
            #pragma unroll
            for (int q = 0; q < 4; q++) {
                const float* rf = (const float*)&ra[q];
                #pragma unroll
                for (int j = 0; j < 4; j++) As_n[(ac + q * 4 + j) * 256 + ar] = rf[j];
            }
            #pragma unroll
            for (int q = 0; q < 2; q++) {
                const float* bf = (const float*)&rb[q];
                #pragma unroll
                for (int j = 0; j < 4; j++) Bs_n[(bc + q * 4 + j) * 128 + br] = bf[j];
            }
            if (t < NT - 2) {
                #pragma unroll
                for (int q = 0; q < 4; q++) ra[q] = *(const float4*)(aptr + (t + 2) * 32 + q * 4);
                #pragma unroll
                for (int q = 0; q < 2; q++) rb[q] = *(const float4*)(bptr + (t + 2) * 32 + q * 4);
            }
        }
        __syncthreads();
    }

    float4 bev0 = *(const float4*)(benc + n0 + tx4);
    float4 bev1 = *(const float4*)(benc + n0 + 64 + tx4);
    #pragma unroll
    for (int i = 0; i < 8; i++) {
        size_t row = (size_t)(m0 + ty8 + i);
        float4 p0 = *(const float4*)(C + row * N_LAT + n0 + tx4);
        float4 p1 = *(const float4*)(C + row * N_LAT + n0 + 64 + tx4);
        unsigned long long s0, s1, s2, s3;
        s0 = packf2(p0.x, p0.y); s1 = packf2(p0.z, p0.w);
        s2 = packf2(p1.x, p1.y); s3 = packf2(p1.z, p1.w);
        ADD2(s0, s0, acc[i][0]);
        ADD2(s1, s1, acc[i][1]);
        ADD2(s2, s2, acc[i][2]);
        ADD2(s3, s3, acc[i][3]);
        float4 o0, o1;
        o0.x = fmaxf(f2lo(s0) + bev0.x, 0.f);
        o0.y = fmaxf(f2hi(s0) + bev0.y, 0.f);
        o0.z = fmaxf(f2lo(s1) + bev0.z, 0.f);
        o0.w = fmaxf(f2hi(s1) + bev0.w, 0.f);
        o1.x = fmaxf(f2lo(s2) + bev1.x, 0.f);
        o1.y = fmaxf(f2hi(s2) + bev1.y, 0.f);
        o1.z = fmaxf(f2lo(s3) + bev1.z, 0.f);
        o1.w = fmaxf(f2hi(s3) + bev1.w, 0.f);
        *(float4*)(C + row * N_LAT + n0 + tx4)      = o0;
        *(float4*)(C + row * N_LAT + n0 + 64 + tx4) = o1;
    }
}

// ============================================================
// top-k per row, list-pruned radix select.
// Pass1: copy-in + lvl0 hist (fused). Pass2: full scan -> listA (bins>b0),
// listB + lvl1 hist (bin==b0). Lvl2 / collection / ties touch only listB/listC.
// Exact jax.lax.top_k semantics (desc value, asc index on ties).
// ============================================================
#define CAP_B 4096
#define CAP_C 1024
#define TOPK_SMEM ((32768 + 2048 + CAP_B + CAP_C) * 4)

__device__ __forceinline__ void select_bin(uint32_t* hist, int nbins, int Kr,
                                           int* csum, int* s_b, int* s_kr, int tid)
{
    int nch = nbins >> 3;
    if (tid < nch) {
        int s = 0;
        #pragma unroll
        for (int j = 0; j < 8; j++) s += (int)hist[tid * 8 + j];
        csum[tid] = s;
    }
    __syncthreads();
    if (tid == 0) {
        int acc = 0, c = nch - 1;
        for (; c > 0; c--) {
            if (acc + csum[c] >= Kr) break;
            acc += csum[c];
        }
        int b = c * 8 + 7;
        for (; b > c * 8; b--) {
            int h = (int)hist[b];
            if (acc + h >= Kr) break;
            acc += h;
        }
        *s_b = b;
        *s_kr = Kr - acc;
    }
    __syncthreads();
}

__global__ void topk_kernel(const float* __restrict__ feat,
                            float* __restrict__ p_ta, float* __restrict__ p_ti)
{
    extern __shared__ uint32_t dyn[];
    uint32_t* sv    = dyn;                 // 32768
    uint32_t* hist  = sv + 32768;          // 2048
    uint32_t* listB = hist + 2048;         // CAP_B (indices, bin==b0)
    uint32_t* listC = listB + CAP_B;       // CAP_C (indices, bin==b0 && mid==b1)

    __shared__ int   csum[256];
    __shared__ int   red[256];
    __shared__ float pv[64];
    __shared__ int   pi[64];
    __shared__ int   listA[64];
    __shared__ int   tiesel[64];
    __shared__ int   s_b, s_kr, s_cntA, s_cntB, s_cntC, s_last;

    int tid = threadIdx.x;
    int row = blockIdx.x;

    // zero lvl0 hist
    for (int i = tid; i < 2048; i += 256) hist[i] = 0;
    if (tid == 0) { s_cntA = 0; s_cntB = 0; s_cntC = 0; }
    __syncthreads();

    // ---- pass 1: copy-in + lvl0 histogram (bits [31:21]) ----
    const float4* src = (const float4*)(feat + (size_t)row * N_LAT);
    uint4* dst = (uint4*)sv;
    int zloc = 0;
    for (int i = tid; i < N_LAT / 4; i += 256) {
        float4 v = src[i];
        uint4 u;
        u.x = __float_as_uint(v.x); u.y = __float_as_uint(v.y);
        u.z = __float_as_uint(v.z); u.w = __float_as_uint(v.w);
        dst[i] = u;
        if (u.x) atomicAdd(&hist[u.x >> 21], 1u); else zloc++;
        if (u.y) atomicAdd(&hist[u.y >> 21], 1u); else zloc++;
        if (u.z) atomicAdd(&hist[u.z >> 21], 1u); else zloc++;
        if (u.w) atomicAdd(&hist[u.w >> 21], 1u); else zloc++;
    }
    if (zloc) atomicAdd(&hist[0], (uint32_t)zloc);
    __syncthreads();

    select_bin(hist, 2048, TOPK, csum, &s_b, &s_kr, tid);
    int b0 = s_b, K1 = s_kr;

    // zero lvl1 hist
    for (int i = tid; i < 2048; i += 256) hist[i] = 0;
    __syncthreads();

    // ---- pass 2: full scan -> listA (bin > b0), listB + lvl1 hist (bin == b0) ----
    for (int i = tid; i < N_LAT; i += 256) {
        uint32_t u = sv[i];
        int b = (int)(u >> 21);
        if (b > b0) {
            int p = atomicAdd(&s_cntA, 1);
            if (p < 64) listA[p] = i;
        } else if (b == b0) {
            int p = atomicAdd(&s_cntB, 1);
            if (p < CAP_B) listB[p] = i;
            atomicAdd(&hist[(u >> 10) & 0x7FF], 1u);
        }
    }
    __syncthreads();
    int cB = s_cntB;

    select_bin(hist, 2048, K1, csum, &s_b, &s_kr, tid);
    int b1 = s_b, K2 = s_kr;

    // zero lvl2 hist (1024 bins)
    for (int i = tid; i < 1024; i += 256) hist[i] = 0;
    __syncthreads();

    // ---- pass 3: over listB (or full fallback) -> listA (mid > b1), listC + lvl2 hist ----
    if (cB <= CAP_B) {
        for (int j = tid; j < cB; j += 256) {
            int i = (int)listB[j];
            uint32_t u = sv[i];
            int mid = (int)((u >> 10) & 0x7FF);
            if (mid > b1) {
                int p = atomicAdd(&s_cntA, 1);
                if (p < 64) listA[p] = i;
            } else if (mid == b1) {
                int p = atomicAdd(&s_cntC, 1);
                if (p < CAP_C) listC[p] = i;
                atomicAdd(&hist[u & 0x3FF], 1u);
            }
        }
    } else {
        for (int i = tid; i < N_LAT; i += 256) {
            uint32_t u = sv[i];
            if ((int)(u >> 21) != b0) continue;
            int mid = (int)((u >> 10) & 0x7FF);
            if (mid > b1) {
                int p = atomicAdd(&s_cntA, 1);
                if (p < 64) listA[p] = i;
            } else if (mid == b1) {
                int p = atomicAdd(&s_cntC, 1);
                if (p < CAP_C) listC[p] = i;
                atomicAdd(&hist[u & 0x3FF], 1u);
            }
        }
    }
    __syncthreads();
    int cC = s_cntC;

    select_bin(hist, 1024, K2, csum, &s_b, &s_kr, tid);
    int b2 = s_b, Need = s_kr;
    uint32_t T = ((uint32_t)b0 << 21) | ((uint32_t)b1 << 10) | (uint32_t)b2;

    // ---- pass 4: collect low > b2 into listA (from listC or fallback) ----
    if (cC <= CAP_C) {
        for (int j = tid; j < cC; j += 256) {
            int i = (int)listC[j];
            uint32_t u = sv[i];
            if ((int)(u & 0x3FF) > b2) {
                int p = atomicAdd(&s_cntA, 1);
                if (p < 64) listA[p] = i;
            }
        }
    } else {
        uint32_t pref = ((uint32_t)b0 << 11) | (uint32_t)b1;  // u >> 10 for mid==b1 within b0
        for (int i = tid; i < N_LAT; i += 256) {
            uint32_t u = sv[i];
            if ((u >> 10) != pref) continue;
            if ((int)(u & 0x3FF) > b2) {
                int p = atomicAdd(&s_cntA, 1);
                if (p < 64) listA[p] = i;
            }
        }
    }
    __syncthreads();
    int cA = s_cntA;

    // ---- ties: pick `Need` smallest indices with value == T ----
    int last = -1;
    for (int s = 0; s < Need; s++) {
        int loc = 0x7FFFFFFF;
        if (cC <= CAP_C) {
            for (int j = tid; j < cC; j += 256) {
                int ix = (int)listC[j];
                if (sv[ix] == T && ix > last && ix < loc) loc = ix;
            }
        } else {
            for (int i = tid; i < N_LAT; i += 256) {
                if (sv[i] == T && i > last && i < loc) loc = i;
            }
        }
        red[tid] = loc;
        __syncthreads();
        for (int st = 128; st > 0; st >>= 1) {
            if (tid < st) red[tid] = min(red[tid], red[tid + st]);
            __syncthreads();
        }
        if (tid == 0) { tiesel[s] = red[0]; s_last = red[0]; }
        __syncthreads();
        last = s_last;
    }

    // ---- rank + write (descending value, ascending index on ties) ----
    if (tid < 64) {
        float v; int ix;
        if (tid < cA) { ix = listA[tid]; v = __uint_as_float(sv[ix]); }
        else          { ix = tiesel[tid - cA]; v = __uint_as_float(T); }
        pv[tid] = v; pi[tid] = ix;
    }
    __syncthreads();
    if (tid < 64) {
        float v = pv[tid]; int ix = pi[tid];
        int rank = 0;
        #pragma unroll 8
        for (int j = 0; j < 64; j++) {
            float vj = pv[j]; int ij = pi[j];
            if (vj > v || (vj == v && ij < ix)) rank++;
        }
        size_t o = (size_t)row * TOPK + rank;
        g_top_val[o] = v;
        g_top_idx[o] = ix;
        if (p_ta) p_ta[o] = v;
        if (p_ti) p_ti[o] = (float)ix;
    }
}

// ============================================================
__global__ void decode_kernel(const float* __restrict__ X,
                              const float* __restrict__ Wd,
                              const float* __restrict__ bdec,
                              float* __restrict__ sae)
{
    __shared__ float sval[64];
    __shared__ int   sidx[64];
    __shared__ float red[256];
    int tid = threadIdx.x, row = blockIdx.x;
    if (tid < 64) {
        sval[tid] = g_top_val[row * TOPK + tid];
        sidx[tid] = g_top_idx[row * TOPK + tid];
    }
    __syncthreads();
    int d0 = tid * 4;
    float4 acc = *(const float4*)(bdec + d0);
    #pragma unroll 4
    for (int k = 0; k < TOPK; k++) {
        float a = sval[k];
        float4 w = *(const float4*)(Wd + (size_t)sidx[k] * D_DIM + d0);
        acc.x += a * w.x; acc.y += a * w.y; acc.z += a * w.z; acc.w += a * w.w;
    }
    size_t o = (size_t)row * D_DIM + d0;
    if (sae) *(float4*)(sae + o) = acc;
    float4 xv = *(const float4*)(X + o);
    float ex = acc.x - xv.x, ey = acc.y - xv.y, ez = acc.z - xv.z, ew = acc.w - xv.w;
    red[tid] = ex * ex + ey * ey + ez * ez + ew * ew;
    __syncthreads();
    for (int st = 128; st > 0; st >>= 1) {
        if (tid < st) red[tid] += red[tid + st];
        __syncthreads();
    }
    if (tid == 0) atomicAdd(&g_acc[0], red[0]);
}

// ============================================================
__global__ void finalize_kernel(float* __restrict__ p_sc) {
    __shared__ float red[256];
    int tid = threadIdx.x;
    float s = 0.f;
    for (int i = tid; i < D_DIM; i += 256) {
        float cs = g_colsum[i];
        s += cs * cs;
    }
    red[tid] = s;
    __syncthreads();
    for (int st = 128; st > 0; st >>= 1) {
        if (tid < st) red[tid] += red[tid + st];
        __syncthreads();
    }
    if (tid == 0) {
        float TV  = g_acc[1] - red[0] / (float)B_N;
        float SSE = g_acc[0];
        p_sc[0] = SSE / TV;
        p_sc[1] = 0.f;
        p_sc[2] = 0.f;
        p_sc[3] = 0.f;
        p_sc[4] = SSE / (float)B_N;
    }
}

// ============================================================
extern "C" void kernel_launch(void* const* d_in, const int* in_sizes, int n_in,
                              void* d_out, int out_size)
{
    const float *x = nullptr, *We = nullptr, *be = nullptr, *Wd = nullptr, *bd = nullptr;
    int big_seen = 0;
    for (int i = 0; i < n_in; i++) {
        int sz = in_sizes[i];
        const float* p = (const float*)d_in[i];
        if (sz == (int)SZ_SAE)          x = p;
        else if (sz == N_LAT * D_DIM)   { if (big_seen++ == 0) We = p; else Wd = p; }
        else if (sz == N_LAT)           be = p;
        else if (sz == D_DIM)           bd = p;
    }

    float* out = (float*)d_out;
    float *p_sae = nullptr, *p_feat = nullptr, *p_ta = nullptr, *p_ti = nullptr, *p_sc = nullptr;

    if ((size_t)out_size == TOTAL_FULL) {
        p_sae  = out;
        p_feat = out + SZ_SAE;
        p_ta   = out + SZ_SAE + SZ_FEAT;
        p_ti   = p_ta + SZ_TA;
        p_sc   = p_ti + SZ_TA;
    } else if ((size_t)out_size == TOTAL_NOFEAT) {
        p_sae = out;
        p_ta  = out + SZ_SAE;
        p_ti  = p_ta + SZ_TA;
        p_sc  = p_ti + SZ_TA;
    } else {
        p_sae = out;
    }

    if (!p_feat) {
        void* fp = nullptr;
        cudaGetSymbolAddress(&fp, g_feat_fallback);
        p_feat = (float*)fp;
    }

    init_kernel<<<4, 256>>>();
    xc_kernel<<<(B_N * D_DIM / 4) / 256, 256>>>(x, bd);
    colstats_kernel<<<dim3(4, 16), 256>>>(x);
    cudaFuncSetAttribute(encode_gemm, cudaFuncAttributeMaxDynamicSharedMemorySize, 98304);
    encode_gemm<<<dim3(B_N / 256, N_LAT / 128), 512, 98304>>>(We, be, p_feat);
    cudaFuncSetAttribute(topk_kernel, cudaFuncAttributeMaxDynamicSharedMemorySize, TOPK_SMEM);
    topk_kernel<<<B_N, 256, TOPK_SMEM>>>(p_feat, p_ta, p_ti);
    decode_kernel<<<B_N, 256>>>(x, Wd, bd, p_sae);
    if (p_sc) finalize_kernel<<<1, 256>>>(p_sc);
}

// round 14
// speedup vs baseline: 1.8776x; 1.1433x over previous
#include <cuda_runtime.h>
#include <cstdint>

#define B_N   4096
#define D_DIM 1024
#define N_LAT 32768
#define TOPK  64

// frozen arithmetic: 2 k-panels of 512, fresh acc, fl(P0+P1), +b_enc, relu
#define NT 32                 // k-tiles of 32
#define TILES_PER_CHUNK 16    // 512/32

// ---- output layout (flattened tuple concat, f32) ----
#define SZ_SAE  ((size_t)B_N * D_DIM)
#define SZ_FEAT ((size_t)B_N * N_LAT)
#define SZ_TA   ((size_t)B_N * TOPK)
#define TOTAL_FULL (SZ_SAE + SZ_FEAT + SZ_TA + SZ_TA + 5)
#define TOTAL_NOFEAT (SZ_SAE + SZ_TA + SZ_TA + 5)

// ---- scratch ----
__device__ float g_top_val[B_N * TOPK];
__device__ int   g_top_idx[B_N * TOPK];
__device__ float g_colsum[D_DIM];
__device__ float g_acc[4];
__device__ float g_xc[(size_t)B_N * D_DIM];          // x - b_dec
__device__ float g_feat_fallback[(size_t)B_N * N_LAT];

#define FMA2(c,a,b) asm("fma.rn.f32x2 %0, %1, %2, %3;" : "=l"(c) : "l"(a), "l"(b), "l"(c))
#define ADD2(c,a,b) asm("add.rn.f32x2 %0, %1, %2;"     : "=l"(c) : "l"(a), "l"(b))
#define PAIR(d,f)   asm("mov.b64 %0, {%1, %1};"        : "=l"(d) : "r"(__float_as_uint(f)))

__device__ __forceinline__ float f2lo(unsigned long long v) { return __uint_as_float((unsigned)v); }
__device__ __forceinline__ float f2hi(unsigned long long v) { return __uint_as_float((unsigned)(v >> 32)); }
__device__ __forceinline__ unsigned long long packf2(float lo, float hi) {
    return ((unsigned long long)__float_as_uint(hi) << 32) | __float_as_uint(lo);
}

// ============================================================
__global__ void init_kernel() {
    int i = blockIdx.x * 256 + threadIdx.x;
    if (i < D_DIM) g_colsum[i] = 0.0f;
    if (i < 4) g_acc[i] = 0.0f;
}

// xc = x - b_dec (elementwise, same fl as reference)
__global__ void xc_kernel(const float* __restrict__ X, const float* __restrict__ bdec) {
    int i = blockIdx.x * blockDim.x + threadIdx.x;      // float4 index
    float4 v = ((const float4*)X)[i];
    float4 d = ((const float4*)bdec)[i & 255];
    v.x -= d.x; v.y -= d.y; v.z -= d.z; v.w -= d.w;
    ((float4*)g_xc)[i] = v;
}

// ============================================================
// column stats, parallel over row chunks: grid (4, 16), 256 thr
__global__ void colstats_kernel(const float* __restrict__ X) {
    __shared__ float redq[256];
    int c  = blockIdx.x * 256 + threadIdx.x;
    int r0 = blockIdx.y * 256;
    float s = 0.f, q = 0.f;
    #pragma unroll 4
    for (int n = r0; n < r0 + 256; n++) {
        float v = X[(size_t)n * D_DIM + c];
        s += v;
        q += v * v;
    }
    atomicAdd(&g_colsum[c], s);
    redq[threadIdx.x] = q;
    __syncthreads();
    for (int st = 128; st > 0; st >>= 1) {
        if (threadIdx.x < st) redq[threadIdx.x] += redq[threadIdx.x + st];
        __syncthreads();
    }
    if (threadIdx.x == 0) atomicAdd(&g_acc[1], redq[0]);
}

// ============================================================
// encode GEMM (unchanged from R12 winner)
// ============================================================
__global__ __launch_bounds__(512, 1)
void encode_gemm(const float* __restrict__ W,
                 const float* __restrict__ benc,
                 float* __restrict__ C)
{
    extern __shared__ char smem_raw[];
    float* As = (float*)smem_raw;                 // [2][32][256] = 64KB
    float* Bs = (float*)(smem_raw + 65536);       // [2][32][128] = 32KB

    int tid = threadIdx.x;
    int tx  = tid & 15;
    int ty  = tid >> 4;
    int ty8 = ty * 8;
    int tx4 = tx * 4;
    int m0 = blockIdx.x * 256;
    int n0 = blockIdx.y * 128;

    int ar = tid >> 1;
    int ac = (tid & 1) << 4;
    int br = tid >> 2;
    int bc = (tid & 3) << 3;

    const float* aptr = g_xc + (size_t)(m0 + ar) * D_DIM + ac;
    const float* bptr = W    + (size_t)(n0 + br) * D_DIM + bc;

    float4 ra[4], rb[2];

    #pragma unroll
    for (int q = 0; q < 4; q++) ra[q] = *(const float4*)(aptr + q * 4);
    #pragma unroll
    for (int q = 0; q < 2; q++) rb[q] = *(const float4*)(bptr + q * 4);
    #pragma unroll
    for (int q = 0; q < 4; q++) {
        const float* rf = (const float*)&ra[q];
        #pragma unroll
        for (int j = 0; j < 4; j++) As[(ac + q * 4 + j) * 256 + ar] = rf[j];
    }
    #pragma unroll
    for (int q = 0; q < 2; q++) {
        const float* bf = (const float*)&rb[q];
        #pragma unroll
        for (int j = 0; j < 4; j++) Bs[(bc + q * 4 + j) * 128 + br] = bf[j];
    }
    #pragma unroll
    for (int q = 0; q < 4; q++) ra[q] = *(const float4*)(aptr + 32 + q * 4);
    #pragma unroll
    for (int q = 0; q < 2; q++) rb[q] = *(const float4*)(bptr + 32 + q * 4);
    __syncthreads();

    unsigned long long acc[8][4];
    #pragma unroll
    for (int i = 0; i < 8; i++)
        #pragma unroll
        for (int j = 0; j < 4; j++) acc[i][j] = 0ULL;

    for (int t = 0; t < NT; t++) {
        int s = t & 1;
        const float* As_s = As + s * 8192;
        const float* Bs_s = Bs + s * 4096;
        #pragma unroll
        for (int kk = 0; kk < 32; kk++) {
            float4 a03 = *(const float4*)(As_s + kk * 256 + ty8);
            float4 a47 = *(const float4*)(As_s + kk * 256 + ty8 + 4);
            ulonglong2 bl = *(const ulonglong2*)(Bs_s + kk * 128 + tx4);
            ulonglong2 bh = *(const ulonglong2*)(Bs_s + kk * 128 + 64 + tx4);
            unsigned long long a2;
            PAIR(a2, a03.x);
            FMA2(acc[0][0], a2, bl.x); FMA2(acc[0][1], a2, bl.y);
            FMA2(acc[0][2], a2, bh.x); FMA2(acc[0][3], a2, bh.y);
            PAIR(a2, a03.y);
            FMA2(acc[1][0], a2, bl.x); FMA2(acc[1][1], a2, bl.y);
            FMA2(acc[1][2], a2, bh.x); FMA2(acc[1][3], a2, bh.y);
            PAIR(a2, a03.z);
            FMA2(acc[2][0], a2, bl.x); FMA2(acc[2][1], a2, bl.y);
            FMA2(acc[2][2], a2, bh.x); FMA2(acc[2][3], a2, bh.y);
            PAIR(a2, a03.w);
            FMA2(acc[3][0], a2, bl.x); FMA2(acc[3][1], a2, bl.y);
            FMA2(acc[3][2], a2, bh.x); FMA2(acc[3][3], a2, bh.y);
            PAIR(a2, a47.x);
            FMA2(acc[4][0], a2, bl.x); FMA2(acc[4][1], a2, bl.y);
            FMA2(acc[4][2], a2, bh.x); FMA2(acc[4][3], a2, bh.y);
            PAIR(a2, a47.y);
            FMA2(acc[5][0], a2, bl.x); FMA2(acc[5][1], a2, bl.y);
            FMA2(acc[5][2], a2, bh.x); FMA2(acc[5][3], a2, bh.y);
            PAIR(a2, a47.z);
            FMA2(acc[6][0], a2, bl.x); FMA2(acc[6][1], a2, bl.y);
            FMA2(acc[6][2], a2, bh.x); FMA2(acc[6][3], a2, bh.y);
            PAIR(a2, a47.w);
            FMA2(acc[7][0], a2, bl.x); FMA2(acc[7][1], a2, bl.y);
            FMA2(acc[7][2], a2, bh.x); FMA2(acc[7][3], a2, bh.y);
        }

        if (t == TILES_PER_CHUNK - 1) {
            #pragma unroll
            for (int i = 0; i < 8; i++) {
                size_t row = (size_t)(m0 + ty8 + i);
                float4 p0, p1;
                p0.x = f2lo(acc[i][0]); p0.y = f2hi(acc[i][0]);
                p0.z = f2lo(acc[i][1]); p0.w = f2hi(acc[i][1]);
                p1.x = f2lo(acc[i][2]); p1.y = f2hi(acc[i][2]);
                p1.z = f2lo(acc[i][3]); p1.w = f2hi(acc[i][3]);
                *(float4*)(C + row * N_LAT + n0 + tx4)      = p0;
                *(float4*)(C + row * N_LAT + n0 + 64 + tx4) = p1;
                #pragma unroll
                for (int j = 0; j < 4; j++) acc[i][j] = 0ULL;
            }
        }

        if (t < NT - 1) {
            int sn = (t + 1) & 1;
            float* As_n = As + sn * 8192;
            float* Bs_n = Bs + sn * 4096;
            #pragma unroll
            for (int q = 0; q < 4; q++) {
                const float* rf = (const float*)&ra[q];
                #pragma unroll
                for (int j = 0; j < 4; j++) As_n[(ac + q * 4 + j) * 256 + ar] = rf[j];
            }
            #pragma unroll
            for (int q = 0; q < 2; q++) {
                const float* bf = (const float*)&rb[q];
                #pragma unroll
                for (int j = 0; j < 4; j++) Bs_n[(bc + q * 4 + j) * 128 + br] = bf[j];
            }
            if (t < NT - 2) {
                #pragma unroll
                for (int q = 0; q < 4; q++) ra[q] = *(const float4*)(aptr + (t + 2) * 32 + q * 4);
                #pragma unroll
                for (int q = 0; q < 2; q++) rb[q] = *(const float4*)(bptr + (t + 2) * 32 + q * 4);
            }
        }
        __syncthreads();
    }

    float4 bev0 = *(const float4*)(benc + n0 + tx4);
    float4 bev1 = *(const float4*)(benc + n0 + 64 + tx4);
    #pragma unroll
    for (int i = 0; i < 8; i++) {
        size_t row = (size_t)(m0 + ty8 + i);
        float4 p0 = *(const float4*)(C + row * N_LAT + n0 + tx4);
        float4 p1 = *(const float4*)(C + row * N_LAT + n0 + 64 + tx4);
        unsigned long long s0, s1, s2, s3;
        s0 = packf2(p0.x, p0.y); s1 = packf2(p0.z, p0.w);
        s2 = packf2(p1.x, p1.y); s3 = packf2(p1.z, p1.w);
        ADD2(s0, s0, acc[i][0]);
        ADD2(s1, s1, acc[i][1]);
        ADD2(s2, s2, acc[i][2]);
        ADD2(s3, s3, acc[i][3]);
        float4 o0, o1;
        o0.x = fmaxf(f2lo(s0) + bev0.x, 0.f);
        o0.y = fmaxf(f2hi(s0) + bev0.y, 0.f);
        o0.z = fmaxf(f2lo(s1) + bev0.z, 0.f);
        o0.w = fmaxf(f2hi(s1) + bev0.w, 0.f);
        o1.x = fmaxf(f2lo(s2) + bev1.x, 0.f);
        o1.y = fmaxf(f2hi(s2) + bev1.y, 0.f);
        o1.z = fmaxf(f2lo(s3) + bev1.z, 0.f);
        o1.w = fmaxf(f2hi(s3) + bev1.w, 0.f);
        *(float4*)(C + row * N_LAT + n0 + tx4)      = o0;
        *(float4*)(C + row * N_LAT + n0 + 64 + tx4) = o1;
    }
}

// ============================================================
// top-k per row, NO resident row copy: pass1 gmem + lvl0 hist; pass2 gmem
// re-read (L2 hot) -> candidate lists (u,idx); lvl1/lvl2/ties on lists only.
// smem ~50KB -> 4 CTAs/SM. Exact jax.lax.top_k tie semantics.
// ============================================================
#define CAP_B 4096
#define CAP_C 1024
#define TOPK_SMEM ((2048 + 2*CAP_B + 2*CAP_C) * 4)

__device__ __forceinline__ void select_bin(uint32_t* hist, int nbins, int Kr,
                                           int* csum, int* s_b, int* s_kr, int tid)
{
    int nch = nbins >> 3;
    if (tid < nch) {
        int s = 0;
        #pragma unroll
        for (int j = 0; j < 8; j++) s += (int)hist[tid * 8 + j];
        csum[tid] = s;
    }
    __syncthreads();
    if (tid == 0) {
        int acc = 0, c = nch - 1;
        for (; c > 0; c--) {
            if (acc + csum[c] >= Kr) break;
            acc += csum[c];
        }
        int b = c * 8 + 7;
        for (; b > c * 8; b--) {
            int h = (int)hist[b];
            if (acc + h >= Kr) break;
            acc += h;
        }
        *s_b = b;
        *s_kr = Kr - acc;
    }
    __syncthreads();
}

__global__ void topk_kernel(const float* __restrict__ feat,
                            float* __restrict__ p_ta, float* __restrict__ p_ti)
{
    extern __shared__ uint32_t dyn[];
    uint32_t* hist    = dyn;                 // 2048
    uint32_t* listB_u = hist + 2048;         // CAP_B
    uint32_t* listB_i = listB_u + CAP_B;     // CAP_B
    uint32_t* listC_u = listB_i + CAP_B;     // CAP_C
    uint32_t* listC_i = listC_u + CAP_C;     // CAP_C

    __shared__ int   csum[256];
    __shared__ int   red[256];
    __shared__ float pv[64];
    __shared__ int   pi[64];
    __shared__ int   listA[64];
    __shared__ int   tiesel[64];
    __shared__ int   s_b, s_kr, s_cntA, s_cntB, s_cntC, s_last;

    int tid = threadIdx.x;
    int row = blockIdx.x;
    const uint4* src = (const uint4*)(feat + (size_t)row * N_LAT);

    for (int i = tid; i < 2048; i += 256) hist[i] = 0;
    if (tid == 0) { s_cntA = 0; s_cntB = 0; s_cntC = 0; }
    __syncthreads();

    // ---- pass 1: gmem read + lvl0 histogram (bits [31:21]) ----
    int zloc = 0;
    for (int i = tid; i < N_LAT / 4; i += 256) {
        uint4 u = src[i];
        if (u.x) atomicAdd(&hist[u.x >> 21], 1u); else zloc++;
        if (u.y) atomicAdd(&hist[u.y >> 21], 1u); else zloc++;
        if (u.z) atomicAdd(&hist[u.z >> 21], 1u); else zloc++;
        if (u.w) atomicAdd(&hist[u.w >> 21], 1u); else zloc++;
    }
    if (zloc) atomicAdd(&hist[0], (uint32_t)zloc);
    __syncthreads();

    select_bin(hist, 2048, TOPK, csum, &s_b, &s_kr, tid);
    int b0 = s_b, K1 = s_kr;

    for (int i = tid; i < 2048; i += 256) hist[i] = 0;
    __syncthreads();

    // ---- pass 2: gmem re-read (L2 hot) -> listA / listB + lvl1 hist ----
    for (int i = tid; i < N_LAT / 4; i += 256) {
        uint4 u = src[i];
        uint32_t uv[4] = {u.x, u.y, u.z, u.w};
        #pragma unroll
        for (int e = 0; e < 4; e++) {
            uint32_t v = uv[e];
            int b = (int)(v >> 21);
            if (b > b0) {
                int p = atomicAdd(&s_cntA, 1);
                if (p < 64) listA[p] = i * 4 + e;
            } else if (b == b0) {
                int p = atomicAdd(&s_cntB, 1);
                if (p < CAP_B) { listB_u[p] = v; listB_i[p] = i * 4 + e; }
                atomicAdd(&hist[(v >> 10) & 0x7FF], 1u);
            }
        }
    }
    __syncthreads();
    int cB = s_cntB;

    select_bin(hist, 2048, K1, csum, &s_b, &s_kr, tid);
    int b1 = s_b, K2 = s_kr;

    for (int i = tid; i < 1024; i += 256) hist[i] = 0;
    __syncthreads();

    // ---- pass 3: listB (or gmem fallback) -> listA / listC + lvl2 hist ----
    if (cB <= CAP_B) {
        for (int j = tid; j < cB; j += 256) {
            uint32_t v = listB_u[j];
            int mid = (int)((v >> 10) & 0x7FF);
            if (mid > b1) {
                int p = atomicAdd(&s_cntA, 1);
                if (p < 64) listA[p] = (int)listB_i[j];
            } else if (mid == b1) {
                int p = atomicAdd(&s_cntC, 1);
                if (p < CAP_C) { listC_u[p] = v; listC_i[p] = listB_i[j]; }
                atomicAdd(&hist[v & 0x3FF], 1u);
            }
        }
    } else {
        const uint32_t* sf = (const uint32_t*)src;
        for (int i = tid; i < N_LAT; i += 256) {
            uint32_t v = sf[i];
            if ((int)(v >> 21) != b0) continue;
            int mid = (int)((v >> 10) & 0x7FF);
            if (mid > b1) {
                int p = atomicAdd(&s_cntA, 1);
                if (p < 64) listA[p] = i;
            } else if (mid == b1) {
                int p = atomicAdd(&s_cntC, 1);
                if (p < CAP_C) { listC_u[p] = v; listC_i[p] = (uint32_t)i; }
                atomicAdd(&hist[v & 0x3FF], 1u);
            }
        }
    }
    __syncthreads();
    int cC = s_cntC;

    select_bin(hist, 1024, K2, csum, &s_b, &s_kr, tid);
    int b2 = s_b, Need = s_kr;
    uint32_t T = ((uint32_t)b0 << 21) | ((uint32_t)b1 << 10) | (uint32_t)b2;

    // ---- pass 4: low > b2 -> listA (listC or gmem fallback) ----
    if (cC <= CAP_C) {
        for (int j = tid; j < cC; j += 256) {
            uint32_t v = listC_u[j];
            if ((int)(v & 0x3FF) > b2) {
                int p = atomicAdd(&s_cntA, 1);
                if (p < 64) listA[p] = (int)listC_i[j];
            }
        }
    } else {
        const uint32_t* sf = (const uint32_t*)src;
        uint32_t pref = ((uint32_t)b0 << 11) | (uint32_t)b1;
        for (int i = tid; i < N_LAT; i += 256) {
            uint32_t v = sf[i];
            if ((v >> 10) != pref) continue;
            if ((int)(v & 0x3FF) > b2) {
                int p = atomicAdd(&s_cntA, 1);
                if (p < 64) listA[p] = i;
            }
        }
    }
    __syncthreads();
    int cA = s_cntA;

    // ---- ties: `Need` smallest indices with value == T ----
    int last = -1;
    for (int s = 0; s < Need; s++) {
        int loc = 0x7FFFFFFF;
        if (cC <= CAP_C) {
            for (int j = tid; j < cC; j += 256) {
                if (listC_u[j] == T) {
                    int ix = (int)listC_i[j];
                    if (ix > last && ix < loc) loc = ix;
                }
            }
        } else {
            const uint32_t* sf = (const uint32_t*)src;
            for (int i = tid; i < N_LAT; i += 256) {
                if (sf[i] == T && i > last && i < loc) loc = i;
            }
        }
        red[tid] = loc;
        __syncthreads();
        for (int st = 128; st > 0; st >>= 1) {
            if (tid < st) red[tid] = min(red[tid], red[tid + st]);
            __syncthreads();
        }
        if (tid == 0) { tiesel[s] = red[0]; s_last = red[0]; }
        __syncthreads();
        last = s_last;
    }

    // ---- rank + write (descending value, ascending index on ties) ----
    if (tid < 64) {
        float v; int ix;
        if (tid < cA) { ix = listA[tid]; v = feat[(size_t)row * N_LAT + ix]; }
        else          { ix = tiesel[tid - cA]; v = __uint_as_float(T); }
        pv[tid] = v; pi[tid] = ix;
    }
    __syncthreads();
    if (tid < 64) {
        float v = pv[tid]; int ix = pi[tid];
        int rank = 0;
        #pragma unroll 8
        for (int j = 0; j < 64; j++) {
            float vj = pv[j]; int ij = pi[j];
            if (vj > v || (vj == v && ij < ix)) rank++;
        }
        size_t o = (size_t)row * TOPK + rank;
        g_top_val[o] = v;
        g_top_idx[o] = ix;
        if (p_ta) p_ta[o] = v;
        if (p_ti) p_ti[o] = (float)ix;
    }
}

// ============================================================
__global__ void decode_kernel(const float* __restrict__ X,
                              const float* __restrict__ Wd,
                              const float* __restrict__ bdec,
                              float* __restrict__ sae)
{
    __shared__ float sval[64];
    __shared__ int   sidx[64];
    __shared__ float red[256];
    int tid = threadIdx.x, row = blockIdx.x;
    if (tid < 64) {
        sval[tid] = g_top_val[row * TOPK + tid];
        sidx[tid] = g_top_idx[row * TOPK + tid];
    }
    __syncthreads();
    int d0 = tid * 4;
    float4 acc = *(const float4*)(bdec + d0);
    #pragma unroll 4
    for (int k = 0; k < TOPK; k++) {
        float a = sval[k];
        float4 w = *(const float4*)(Wd + (size_t)sidx[k] * D_DIM + d0);
        acc.x += a * w.x; acc.y += a * w.y; acc.z += a * w.z; acc.w += a * w.w;
    }
    size_t o = (size_t)row * D_DIM + d0;
    if (sae) *(float4*)(sae + o) = acc;
    float4 xv = *(const float4*)(X + o);
    float ex = acc.x - xv.x, ey = acc.y - xv.y, ez = acc.z - xv.z, ew = acc.w - xv.w;
    red[tid] = ex * ex + ey * ey + ez * ez + ew * ew;
    __syncthreads();
    for (int st = 128; st > 0; st >>= 1) {
        if (tid < st) red[tid] += red[tid + st];
        __syncthreads();
    }
    if (tid == 0) atomicAdd(&g_acc[0], red[0]);
}

// ============================================================
__global__ void finalize_kernel(float* __restrict__ p_sc) {
    __shared__ float red[256];
    int tid = threadIdx.x;
    float s = 0.f;
    for (int i = tid; i < D_DIM; i += 256) {
        float cs = g_colsum[i];
        s += cs * cs;
    }
    red[tid] = s;
    __syncthreads();
    for (int st = 128; st > 0; st >>= 1) {
        if (tid < st) red[tid] += red[tid + st];
        __syncthreads();
    }
    if (tid == 0) {
        float TV  = g_acc[1] - red[0] / (float)B_N;
        float SSE = g_acc[0];
        p_sc[0] = SSE / TV;
        p_sc[1] = 0.f;
        p_sc[2] = 0.f;
        p_sc[3] = 0.f;
        p_sc[4] = SSE / (float)B_N;
    }
}

// ============================================================
extern "C" void kernel_launch(void* const* d_in, const int* in_sizes, int n_in,
                              void* d_out, int out_size)
{
    const float *x = nullptr, *We = nullptr, *be = nullptr, *Wd = nullptr, *bd = nullptr;
    int big_seen = 0;
    for (int i = 0; i < n_in; i++) {
        int sz = in_sizes[i];
        const float* p = (const float*)d_in[i];
        if (sz == (int)SZ_SAE)          x = p;
        else if (sz == N_LAT * D_DIM)   { if (big_seen++ == 0) We = p; else Wd = p; }
        else if (sz == N_LAT)           be = p;
        else if (sz == D_DIM)           bd = p;
    }

    float* out = (float*)d_out;
    float *p_sae = nullptr, *p_feat = nullptr, *p_ta = nullptr, *p_ti = nullptr, *p_sc = nullptr;

    if ((size_t)out_size == TOTAL_FULL) {
        p_sae  = out;
        p_feat = out + SZ_SAE;
        p_ta   = out + SZ_SAE + SZ_FEAT;
        p_ti   = p_ta + SZ_TA;
        p_sc   = p_ti + SZ_TA;
    } else if ((size_t)out_size == TOTAL_NOFEAT) {
        p_sae = out;
        p_ta  = out + SZ_SAE;
        p_ti  = p_ta + SZ_TA;
        p_sc  = p_ti + SZ_TA;
    } else {
        p_sae = out;
    }

    if (!p_feat) {
        void* fp = nullptr;
        cudaGetSymbolAddress(&fp, g_feat_fallback);
        p_feat = (float*)fp;
    }

    init_kernel<<<4, 256>>>();
    xc_kernel<<<(B_N * D_DIM / 4) / 256, 256>>>(x, bd);
    colstats_kernel<<<dim3(4, 16), 256>>>(x);
    cudaFuncSetAttribute(encode_gemm, cudaFuncAttributeMaxDynamicSharedMemorySize, 98304);
    encode_gemm<<<dim3(B_N / 256, N_LAT / 128), 512, 98304>>>(We, be, p_feat);
    cudaFuncSetAttribute(topk_kernel, cudaFuncAttributeMaxDynamicSharedMemorySize, TOPK_SMEM);
    topk_kernel<<<B_N, 256, TOPK_SMEM>>>(p_feat, p_ta, p_ti);
    decode_kernel<<<B_N, 256>>>(x, Wd, bd, p_sae);
    if (p_sc) finalize_kernel<<<1, 256>>>(p_sc);
}